// round 12
// baseline (speedup 1.0000x reference)
#include <cuda_runtime.h>
#include <cuda_bf16.h>
#include <math.h>
#include <stdint.h>

// ---------------- problem constants ----------------
#define T_STEPS 30
#define BATCH   32
#define HID     512
#define S_LEN   50
#define VOCAB   32000
#define GDIM    1536   // 3*H
#define XK      576    // 512 emb + 64 latent

// ---------------- fp32 scratch ----------------
__device__ float g_kc[S_LEN * BATCH * HID];
__device__ float g_kf[S_LEN * BATCH * HID];
__device__ float g_Pc[S_LEN * BATCH * GDIM];
__device__ float g_Pf[S_LEN * BATCH * GDIM];
__device__ float g_X[T_STEPS * BATCH * XK];
__device__ float g_Wg[GDIM * XK];
__device__ float g_gipre[T_STEPS * BATCH * GDIM];
__device__ float g_q[BATCH * 1024];          // [b][ qc(512) | qf(512) ]
__device__ float g_gh[BATCH * GDIM];
__device__ float g_score[2 * S_LEN * BATCH];
__device__ float g_h[BATCH * HID];
__device__ float g_reluh[T_STEPS * BATCH * HID];
__device__ float g_bstack[2560];             // [cb_h | fb_h | b_hh]

// ---------------- bf16 split (hi/lo) row-major operand buffers ----------------
__device__ __nv_bfloat16 g_cmh[1664 * 512],  g_cml[1664 * 512];
__device__ __nv_bfloat16 g_fmh[1664 * 512],  g_fml[1664 * 512];
__device__ __nv_bfloat16 g_cwmh[512 * 512],  g_cwml[512 * 512];
__device__ __nv_bfloat16 g_fwmh[512 * 512],  g_fwml[512 * 512];
__device__ __nv_bfloat16 g_wcch[1536 * 512], g_wccl[1536 * 512];
__device__ __nv_bfloat16 g_wcfh[1536 * 512], g_wcfl[1536 * 512];
__device__ __nv_bfloat16 g_wgh[1536 * 576],  g_wgl[1536 * 576];
__device__ __nv_bfloat16 g_xh[1024 * 576],   g_xl[1024 * 576];
__device__ __nv_bfloat16 g_rhh[1024 * 512],  g_rhl[1024 * 512];
__device__ __nv_bfloat16 g_wph[32000 * 512], g_wpl[32000 * 512];
__device__ __nv_bfloat16 g_wsh[2560 * 512],  g_wsl[2560 * 512];   // stacked [cW_h; fW_h; W_hh]
__device__ __nv_bfloat16 g_hh[BATCH * 512],  g_hl[BATCH * 512];   // current h split

// ---------------- math helpers ----------------
__device__ __forceinline__ float tanhx(float x) {
    float e = __expf(2.0f * x);
    return 1.0f - __fdividef(2.0f, e + 1.0f);
}
__device__ __forceinline__ float sigx(float x) {
    return __fdividef(1.0f, 1.0f + __expf(-x));
}

// ---------------- PTX helpers (sm_80/sm_90-era, plain-sm_100-safe) ----------------
__device__ __forceinline__ uint32_t smem_u32(const void* p) {
    uint32_t a;
    asm("{ .reg .u64 t; cvta.to.shared.u64 t, %1; cvt.u32.u64 %0, t; }" : "=r"(a) : "l"(p));
    return a;
}
#define CP16(dst, src) asm volatile("cp.async.cg.shared.global [%0], [%1], 16;" :: "r"(dst), "l"(src))
#define CP_COMMIT()    asm volatile("cp.async.commit_group;")
#define CP_WAIT1()     asm volatile("cp.async.wait_group 1;")
#define CP_WAIT0()     asm volatile("cp.async.wait_group 0;")
#define CLUSTER_ARRIVE() asm volatile("barrier.cluster.arrive;" ::: "memory")
#define CLUSTER_WAIT()   asm volatile("barrier.cluster.wait;"   ::: "memory")

__device__ __forceinline__ void ldsm4(uint32_t* r, uint32_t addr) {
    asm volatile("ldmatrix.sync.aligned.m8n8.x4.shared.b16 {%0,%1,%2,%3}, [%4];"
        : "=r"(r[0]), "=r"(r[1]), "=r"(r[2]), "=r"(r[3]) : "r"(addr));
}
__device__ __forceinline__ void mma_bf16(float* d, const uint32_t* a, const uint32_t* b) {
    asm volatile("mma.sync.aligned.m16n8k16.row.col.f32.bf16.bf16.f32 "
        "{%0,%1,%2,%3}, {%4,%5,%6,%7}, {%8,%9}, {%0,%1,%2,%3};"
        : "+f"(d[0]), "+f"(d[1]), "+f"(d[2]), "+f"(d[3])
        : "r"(a[0]), "r"(a[1]), "r"(a[2]), "r"(a[3]), "r"(b[0]), "r"(b[1]));
}

__device__ __forceinline__ void split_bf16(float v, __nv_bfloat16& hi, __nv_bfloat16& lo) {
    hi = __float2bfloat16(v);
    lo = __float2bfloat16(v - __bfloat162float(hi));
}

// ---------------- fused gathers (X, Wg, h(+split), bstack) ----------------
__global__ void gather_all(const int* __restrict__ target,
                           const float* __restrict__ emb,
                           const float* __restrict__ latent,
                           const float* __restrict__ Wih,
                           const float* __restrict__ hidden,
                           const float* __restrict__ cbh,
                           const float* __restrict__ fbh,
                           const float* __restrict__ bhh)
{
    const int bx = blockIdx.x;
    if (bx < 960) {
        const int m = bx;
        const int t = m >> 5, b = m & 31;
        const int tok = (t == 0) ? 1 : target[(t - 1) * BATCH + b];
        float* xr = g_X + (size_t)m * XK;
        const float* er = emb + (size_t)tok * 512;
        for (int c = threadIdx.x; c < XK; c += blockDim.x)
            xr[c] = (c < 512) ? er[c] : latent[b * 64 + (c - 512)];
    } else if (bx < 2496) {
        const int n = bx - 960;
        float* wr = g_Wg + (size_t)n * XK;
        const float* src = Wih + (size_t)n * 1600;
        for (int c = threadIdx.x; c < XK; c += blockDim.x)
            wr[c] = (c < 512) ? src[c] : src[1536 + (c - 512)];
    } else if (bx < 2512) {
        const int i = (bx - 2496) * 256 + threadIdx.x;   // 4096 float4
        float4 v = ((const float4*)hidden)[i];
        ((float4*)g_h)[i] = v;
        __nv_bfloat16 h0, l0, h1, l1, h2, l2, h3, l3;
        split_bf16(v.x, h0, l0); split_bf16(v.y, h1, l1);
        split_bf16(v.z, h2, l2); split_bf16(v.w, h3, l3);
        const int e = i * 4;
        g_hh[e] = h0; g_hh[e + 1] = h1; g_hh[e + 2] = h2; g_hh[e + 3] = h3;
        g_hl[e] = l0; g_hl[e + 1] = l1; g_hl[e + 2] = l2; g_hl[e + 3] = l3;
    } else {
        const int r = (bx - 2512) * 256 + threadIdx.x;
        if (r < 2560) {
            float v;
            if (r < 512)       v = cbh[r];
            else if (r < 1024) v = fbh[r - 512];
            else               v = bhh[r - 1024];
            g_bstack[r] = v;
        }
    }
}

// ---------------- fused fp32 -> split-bf16 conversion (12 jobs, one launch) ----------------
struct ConvJob {
    const float* src;
    int ld, cs, R, K, Rpad;
    __nv_bfloat16 *hi, *lo;
    long base;      // granule prefix
};
struct ConvJobs { ConvJob j[12]; long total; };

__global__ void conv_all(ConvJobs jobs)
{
    for (long idx = (long)blockIdx.x * blockDim.x + threadIdx.x; idx < jobs.total;
         idx += (long)gridDim.x * blockDim.x) {
        int sidx = 11;
        #pragma unroll
        for (int s = 1; s < 12; s++)
            if (idx < jobs.j[s].base) { sidx = s - 1; break; }
        const ConvJob jb = jobs.j[sidx];
        const long local = idx - jb.base;
        const int gpr = jb.K >> 3;
        const int r = (int)(local / gpr);
        const int g = (int)(local - (long)r * gpr);
        float v[8];
        if (r < jb.R) {
            const float* p = jb.src + (size_t)r * jb.ld + jb.cs + g * 8;
            float4 u0 = *(const float4*)p;
            float4 u1 = *(const float4*)(p + 4);
            v[0] = u0.x; v[1] = u0.y; v[2] = u0.z; v[3] = u0.w;
            v[4] = u1.x; v[5] = u1.y; v[6] = u1.z; v[7] = u1.w;
        } else {
            #pragma unroll
            for (int k = 0; k < 8; k++) v[k] = 0.f;
        }
        __align__(16) unsigned short hb[8];
        __align__(16) unsigned short lb[8];
        #pragma unroll
        for (int k = 0; k < 8; k++) {
            __nv_bfloat16 h, l;
            split_bf16(v[k], h, l);
            hb[k] = reinterpret_cast<unsigned short&>(h);
            lb[k] = reinterpret_cast<unsigned short&>(l);
        }
        size_t o = (size_t)r * jb.K + (size_t)g * 8;
        *(uint4*)(jb.hi + o) = *(const uint4*)hb;
        *(uint4*)(jb.lo + o) = *(const uint4*)lb;
    }
}

// ---------------- HMMA split-bf16 NT GEMM tile (exact R4 body as device fn) ----------------
#define ROWB  144
#define TILEA (128 * ROWB)
#define STG   (2 * TILEA)
#define GSMEM (2 * STG)

__device__ __forceinline__ void gemm_tile(
    const __nv_bfloat16* __restrict__ Ah, const __nv_bfloat16* __restrict__ Al,
    const __nv_bfloat16* __restrict__ Bh, const __nv_bfloat16* __restrict__ Bl,
    int K, const float* __restrict__ bias, float* __restrict__ C,
    int Mreal, int Ncols, int outmode, int m0, int n0, char* sm)
{
    const int tid = threadIdx.x;
    const int nch = K >> 6;
    const int niter = 3 * nch;
    const uint32_t base = smem_u32(sm);

    const int lane = tid & 31, w = tid >> 5;
    const int wm = w & 3, wn = w >> 2;

    float acc[2][8][4];
    #pragma unroll
    for (int a = 0; a < 2; a++)
        #pragma unroll
        for (int b = 0; b < 8; b++)
            #pragma unroll
            for (int c = 0; c < 4; c++) acc[a][b][c] = 0.f;

    const int lr[4] = { (tid + 0) >> 3, (tid + 256) >> 3, (tid + 512) >> 3, (tid + 768) >> 3 };
    const int lg = tid & 7;

    auto load_stage = [&](int i, int stage) {
        const int p  = i / nch;
        const int kc = i - p * nch;
        const __nv_bfloat16* Ag = ((p == 1) ? Al : Ah) + (size_t)m0 * K + kc * 64;
        const __nv_bfloat16* Bg = ((p == 2) ? Bl : Bh) + (size_t)n0 * K + kc * 64;
        const uint32_t dA = base + stage * STG;
        const uint32_t dB = dA + TILEA;
        #pragma unroll
        for (int j = 0; j < 4; j++) {
            const int r = lr[j];
            CP16(dA + r * ROWB + lg * 16, Ag + (size_t)r * K + lg * 8);
            CP16(dB + r * ROWB + lg * 16, Bg + (size_t)r * K + lg * 8);
        }
        CP_COMMIT();
    };

    load_stage(0, 0);

    for (int i = 0; i < niter; i++) {
        const int cur = i & 1;
        if (i + 1 < niter) { load_stage(i + 1, cur ^ 1); CP_WAIT1(); }
        else               { CP_WAIT0(); }
        __syncthreads();

        const uint32_t sA = base + cur * STG;
        const uint32_t sB = sA + TILEA;
        const uint32_t aBase = sA + (uint32_t)(wm * 32 + (lane & 15)) * ROWB + (uint32_t)(lane >> 4) * 16;
        const uint32_t bBase = sB + (uint32_t)(wn * 64 + (lane & 7) + ((lane >> 4) << 3)) * ROWB
                                  + (uint32_t)(((lane >> 3) & 1) << 4);

        #pragma unroll
        for (int ks = 0; ks < 4; ks++) {
            uint32_t af[2][4], bfr[4][4];
            ldsm4(af[0], aBase + ks * 32);
            ldsm4(af[1], aBase + 16 * ROWB + ks * 32);
            #pragma unroll
            for (int ni = 0; ni < 4; ni++)
                ldsm4(bfr[ni], bBase + ni * 16 * ROWB + ks * 32);
            #pragma unroll
            for (int mi = 0; mi < 2; mi++)
                #pragma unroll
                for (int ni = 0; ni < 4; ni++) {
                    mma_bf16(acc[mi][2 * ni],     af[mi], &bfr[ni][0]);
                    mma_bf16(acc[mi][2 * ni + 1], af[mi], &bfr[ni][2]);
                }
        }
        __syncthreads();
    }

    const int ncol0 = n0 + wn * 64 + (lane & 3) * 2;
    #pragma unroll
    for (int mi = 0; mi < 2; mi++) {
        const int ml = wm * 32 + mi * 16 + (lane >> 2);
        #pragma unroll
        for (int half = 0; half < 2; half++) {
            const int m = m0 + ml + half * 8;
            if (m >= Mreal) continue;
            size_t orow = outmode ? ((size_t)(m & 31) * T_STEPS + (m >> 5)) : (size_t)m;
            float* cr = C + orow * Ncols + ncol0;
            #pragma unroll
            for (int nj = 0; nj < 8; nj++) {
                const int c = ncol0 + nj * 8;
                float b0 = bias ? bias[c] : 0.f;
                float b1 = bias ? bias[c + 1] : 0.f;
                float2 v;
                v.x = acc[mi][nj][half * 2 + 0] + b0;
                v.y = acc[mi][nj][half * 2 + 1] + b1;
                *(float2*)(cr + nj * 8) = v;
            }
        }
    }
}

// single-job GEMM (projection)
__global__ void __launch_bounds__(256) mma_gemm(
    const __nv_bfloat16* __restrict__ Ah, const __nv_bfloat16* __restrict__ Al,
    const __nv_bfloat16* __restrict__ Bh, const __nv_bfloat16* __restrict__ Bl,
    int K, const float* __restrict__ bias, float* __restrict__ C,
    int Mreal, int Ncols, int outmode)
{
    extern __shared__ __align__(128) char sm[];
    gemm_tile(Ah, Al, Bh, Bl, K, bias, C, Mreal, Ncols, outmode,
              blockIdx.x * 128, blockIdx.y * 128, sm);
}

// all 5 precompute GEMMs in one launch (block-range dispatch)
struct GemmJob {
    const __nv_bfloat16 *Ah, *Al, *Bh, *Bl;
    int K;
    const float* bias;
    float* C;
    int Mreal, Ncols, mw, base;
};
struct GemmJobs { GemmJob j[5]; };

__global__ void __launch_bounds__(256) gemm_all(GemmJobs jobs)
{
    extern __shared__ __align__(128) char sm[];
    const int bx = blockIdx.x;
    int s = 4;
    #pragma unroll
    for (int k = 1; k < 5; k++)
        if (bx < jobs.j[k].base) { s = k - 1; break; }
    const GemmJob jb = jobs.j[s];
    const int i = bx - jb.base;
    const int m0 = (i % jb.mw) * 128;
    const int n0 = (i / jb.mw) * 128;
    gemm_tile(jb.Ah, jb.Al, jb.Bh, jb.Bl, jb.K, jb.bias, jb.C,
              jb.Mreal, jb.Ncols, 0, m0, n0, sm);
}

// ---------------- decode step A via HMMA: [q | gh] = h @ Wstack^T + bstack ----------------
// grid 20 x 256. Block = 32 batches x 128 stacked rows (R9-verified 32x128 tile).
#define P_AROW 4608              // 32 * 144
#define P_STG  23040             // (32 + 128) * 144
#define P_SMEM (2 * P_STG)       // 46080

__global__ void __launch_bounds__(256) step_qghmma()
{
    extern __shared__ __align__(128) char psm[];
    const uint32_t base = smem_u32(psm);
    const int tid = threadIdx.x;
    const int lane = tid & 31;
    const int w = tid >> 5;
    const int n0 = blockIdx.x * 128;

    float acc[2][2][4];
    #pragma unroll
    for (int a = 0; a < 2; a++)
        #pragma unroll
        for (int b = 0; b < 2; b++)
            #pragma unroll
            for (int c = 0; c < 4; c++) acc[a][b][c] = 0.f;

    const int arow = tid >> 3;           // 0..31 (batch)
    const int lg = tid & 7;

    auto load_stage = [&](int i, int stage) {
        const int p  = i >> 3;           // pass: 0 Ah*Bh, 1 Al*Bh, 2 Ah*Bl
        const int kc = i & 7;
        const __nv_bfloat16* Ag = ((p == 1) ? g_hl : g_hh)
            + ((size_t)arow * 512 + kc * 64 + lg * 8);
        const __nv_bfloat16* Bbase = (p == 2) ? g_wsl : g_wsh;
        const uint32_t dA = base + stage * P_STG;
        const uint32_t dB = dA + P_AROW;
        CP16(dA + arow * ROWB + lg * 16, Ag);
        #pragma unroll
        for (int j = 0; j < 4; j++) {
            const int r = arow + 32 * j;
            CP16(dB + r * ROWB + lg * 16,
                 Bbase + ((size_t)(n0 + r) * 512 + kc * 64 + lg * 8));
        }
        CP_COMMIT();
    };

    load_stage(0, 0);

    for (int i = 0; i < 24; i++) {
        const int cur = i & 1;
        if (i + 1 < 24) { load_stage(i + 1, cur ^ 1); CP_WAIT1(); }
        else            { CP_WAIT0(); }
        __syncthreads();

        const uint32_t sA = base + cur * P_STG;
        const uint32_t sB = sA + P_AROW;
        const uint32_t aBase = sA + (uint32_t)(lane & 15) * ROWB + (uint32_t)(lane >> 4) * 16;
        const uint32_t bBase = sB + (uint32_t)(w * 16 + (lane & 7) + ((lane >> 4) << 3)) * ROWB
                                  + (uint32_t)(((lane >> 3) & 1) << 4);

        #pragma unroll
        for (int ks = 0; ks < 4; ks++) {
            uint32_t af0[4], af1[4], bfr[4];
            ldsm4(af0, aBase + ks * 32);
            ldsm4(af1, aBase + 16 * ROWB + ks * 32);
            ldsm4(bfr, bBase + ks * 32);
            mma_bf16(acc[0][0], af0, &bfr[0]);
            mma_bf16(acc[0][1], af0, &bfr[2]);
            mma_bf16(acc[1][0], af1, &bfr[0]);
            mma_bf16(acc[1][1], af1, &bfr[2]);
        }
        __syncthreads();
    }

    const int ncol0 = n0 + w * 16 + (lane & 3) * 2;
    #pragma unroll
    for (int mi = 0; mi < 2; mi++) {
        #pragma unroll
        for (int half = 0; half < 2; half++) {
            const int b = mi * 16 + (lane >> 2) + half * 8;    // batch 0..31
            #pragma unroll
            for (int nj = 0; nj < 2; nj++) {
                #pragma unroll
                for (int e = 0; e < 2; e++) {
                    const int c = ncol0 + nj * 8 + e;          // stacked row
                    const float v = acc[mi][nj][half * 2 + e] + g_bstack[c];
                    if (c < 1024) g_q[b * 1024 + c] = v;
                    else          g_gh[(size_t)b * GDIM + (c - 1024)] = v;
                }
            }
        }
    }
}

// ---------------- fused decode step B+C (exact R10) + h-split emission ----------------
__global__ void __cluster_dims__(4, 1, 1) __launch_bounds__(256) step_scoregate(
    int tstep,
    const float* __restrict__ cWo, const float* __restrict__ cbo,
    const float* __restrict__ fWo, const float* __restrict__ fbo,
    const int* __restrict__ cmask, const int* __restrict__ fmask)
{
    __shared__ float s_all[100];
    __shared__ float attn[2][S_LEN];
    __shared__ float s_ps[384];

    const int qd = blockIdx.x;
    const int b  = blockIdx.y;
    const int tid = threadIdx.x;
    const int lane = tid & 31;
    const int w = tid >> 5;

    for (int ui = w; ui < 25; ui += 8) {
        const int u = qd * 25 + ui;
        const int a = u / S_LEN;
        const int s = u % S_LEN;
        const float* kr = (a ? g_kf : g_kc) + (size_t)(s * BATCH + b) * HID;
        const float* qr = g_q + b * 1024 + a * 512;
        const float* Wo = a ? fWo : cWo;
        float sacc = 0.f;
        #pragma unroll
        for (int j = 0; j < 4; j++) {
            float4 kv = *(const float4*)(kr + j * 128 + lane * 4);
            float4 qv = *(const float4*)(qr + j * 128 + lane * 4);
            float4 wv = *(const float4*)(Wo + j * 128 + lane * 4);
            sacc = fmaf(wv.x, tanhx(qv.x + kv.x), sacc);
            sacc = fmaf(wv.y, tanhx(qv.y + kv.y), sacc);
            sacc = fmaf(wv.z, tanhx(qv.z + kv.z), sacc);
            sacc = fmaf(wv.w, tanhx(qv.w + kv.w), sacc);
        }
        #pragma unroll
        for (int o = 16; o; o >>= 1) sacc += __shfl_xor_sync(0xffffffffu, sacc, o);
        if (lane == 0) {
            const int* msk = a ? fmask : cmask;
            float v = sacc + (a ? fbo : cbo)[0];
            if (msk[s * BATCH + b] == 0) v = -INFINITY;
            __stcg(&g_score[(a * S_LEN + s) * BATCH + b], v);
        }
    }

    CLUSTER_ARRIVE();
    CLUSTER_WAIT();

    if (tid < 100) s_all[tid] = __ldcg(&g_score[tid * BATCH + b]);
    __syncthreads();

    if (w < 2) {
        const int a = w;
        float v0 = s_all[a * S_LEN + lane];
        float v1 = (lane < S_LEN - 32) ? s_all[a * S_LEN + 32 + lane] : -INFINITY;
        float mx = fmaxf(v0, v1);
        #pragma unroll
        for (int o = 16; o; o >>= 1) mx = fmaxf(mx, __shfl_xor_sync(0xffffffffu, mx, o));
        float e0 = __expf(v0 - mx);
        float e1 = (lane < S_LEN - 32) ? __expf(v1 - mx) : 0.f;
        float sm = e0 + e1;
        #pragma unroll
        for (int o = 16; o; o >>= 1) sm += __shfl_xor_sync(0xffffffffu, sm, o);
        float inv = __fdividef(1.f, sm);
        attn[a][lane] = e0 * inv;
        if (lane < S_LEN - 32) attn[a][32 + lane] = e1 * inv;
    }
    __syncthreads();

    const int j = qd * 128 + (tid & 127);
    const int shalf = tid >> 7;
    float gr = 0.f, gz = 0.f, gn = 0.f;
    const int sbeg = shalf * 25;
    #pragma unroll 1
    for (int s = sbeg; s < sbeg + 25; s++) {
        const float ac = attn[0][s];
        const float af = attn[1][s];
        const float* pc = g_Pc + (size_t)(s * BATCH + b) * GDIM;
        const float* pf = g_Pf + (size_t)(s * BATCH + b) * GDIM;
        gr = fmaf(ac, pc[j],        gr); gr = fmaf(af, pf[j],        gr);
        gz = fmaf(ac, pc[512 + j],  gz); gz = fmaf(af, pf[512 + j],  gz);
        gn = fmaf(ac, pc[1024 + j], gn); gn = fmaf(af, pf[1024 + j], gn);
    }
    if (shalf == 1) {
        s_ps[tid & 127]         = gr;
        s_ps[128 + (tid & 127)] = gz;
        s_ps[256 + (tid & 127)] = gn;
    }
    __syncthreads();
    if (shalf == 0) {
        gr += s_ps[tid];
        gz += s_ps[128 + tid];
        gn += s_ps[256 + tid];
        const float* gip = g_gipre + (size_t)(tstep * BATCH + b) * GDIM;
        const float* ghb = g_gh + (size_t)b * GDIM;
        const float gir = gip[j]        + gr;
        const float giz = gip[512 + j]  + gz;
        const float gin = gip[1024 + j] + gn;
        const float r = sigx(gir + ghb[j]);
        const float z = sigx(giz + ghb[512 + j]);
        const float n = tanhx(gin + r * ghb[1024 + j]);
        const float hv = g_h[b * HID + j];
        const float hn = (1.f - z) * n + z * hv;
        g_h[b * HID + j] = hn;
        g_reluh[(size_t)(tstep * BATCH + b) * HID + j] = fmaxf(hn, 0.f);
        __nv_bfloat16 hi, lo;
        split_bf16(hn, hi, lo);
        g_hh[b * 512 + j] = hi;
        g_hl[b * 512 + j] = lo;
    }
}

// single-job conv (reluh, after loop)
__global__ void conv_split(const float* __restrict__ src, int ld, int colstart,
                           int R, int K, int Rpad,
                           __nv_bfloat16* __restrict__ hi, __nv_bfloat16* __restrict__ lo)
{
    const int gpr = K >> 3;
    const long total = (long)Rpad * gpr;
    for (long idx = (long)blockIdx.x * blockDim.x + threadIdx.x; idx < total;
         idx += (long)gridDim.x * blockDim.x) {
        int r = (int)(idx / gpr);
        int g = (int)(idx - (long)r * gpr);
        float v[8];
        if (r < R) {
            const float* p = src + (size_t)r * ld + colstart + g * 8;
            float4 u0 = *(const float4*)p;
            float4 u1 = *(const float4*)(p + 4);
            v[0] = u0.x; v[1] = u0.y; v[2] = u0.z; v[3] = u0.w;
            v[4] = u1.x; v[5] = u1.y; v[6] = u1.z; v[7] = u1.w;
        } else {
            #pragma unroll
            for (int j = 0; j < 8; j++) v[j] = 0.f;
        }
        __align__(16) unsigned short hb[8];
        __align__(16) unsigned short lb[8];
        #pragma unroll
        for (int j = 0; j < 8; j++) {
            __nv_bfloat16 h, l;
            split_bf16(v[j], h, l);
            hb[j] = reinterpret_cast<unsigned short&>(h);
            lb[j] = reinterpret_cast<unsigned short&>(l);
        }
        size_t o = (size_t)r * K + (size_t)g * 8;
        *(uint4*)(hi + o) = *(const uint4*)hb;
        *(uint4*)(lo + o) = *(const uint4*)lb;
    }
}

// ---------------- launcher ----------------
extern "C" void kernel_launch(void* const* d_in, const int* in_sizes, int n_in,
                              void* d_out, int out_size)
{
    (void)in_sizes; (void)n_in; (void)out_size;

    const float* c_memory = (const float*)d_in[0];
    const int*   c_mask   = (const int*)  d_in[1];
    const float* f_memory = (const float*)d_in[2];
    const int*   f_mask   = (const int*)  d_in[3];
    const float* hidden   = (const float*)d_in[4];
    const float* latent   = (const float*)d_in[6];
    const int*   target   = (const int*)  d_in[7];
    const float* emb      = (const float*)d_in[8];
    const float* cW_h = (const float*)d_in[9];
    const float* cb_h = (const float*)d_in[10];
    const float* cW_m = (const float*)d_in[11];
    const float* cb_m = (const float*)d_in[12];
    const float* cW_o = (const float*)d_in[13];
    const float* cb_o = (const float*)d_in[14];
    const float* fW_h = (const float*)d_in[15];
    const float* fb_h = (const float*)d_in[16];
    const float* fW_m = (const float*)d_in[17];
    const float* fb_m = (const float*)d_in[18];
    const float* fW_o = (const float*)d_in[19];
    const float* fb_o = (const float*)d_in[20];
    const float* W_ih = (const float*)d_in[21];
    const float* b_ih = (const float*)d_in[22];
    const float* W_hh = (const float*)d_in[23];
    const float* b_hh = (const float*)d_in[24];
    const float* W_pr = (const float*)d_in[25];
    const float* b_pr = (const float*)d_in[26];
    float* out = (float*)d_out;

    float *kc, *kf, *Pc, *Pf, *X, *Wg, *gipre, *reluh;
    cudaGetSymbolAddress((void**)&kc,    g_kc);
    cudaGetSymbolAddress((void**)&kf,    g_kf);
    cudaGetSymbolAddress((void**)&Pc,    g_Pc);
    cudaGetSymbolAddress((void**)&Pf,    g_Pf);
    cudaGetSymbolAddress((void**)&X,     g_X);
    cudaGetSymbolAddress((void**)&Wg,    g_Wg);
    cudaGetSymbolAddress((void**)&gipre, g_gipre);
    cudaGetSymbolAddress((void**)&reluh, g_reluh);

    __nv_bfloat16 *cmh, *cml, *fmh, *fml, *cwmh, *cwml, *fwmh, *fwml;
    __nv_bfloat16 *wcch, *wccl, *wcfh, *wcfl, *wgh, *wgl, *xh, *xl, *rhh, *rhl, *wph, *wpl;
    __nv_bfloat16 *wsh, *wsl;
    cudaGetSymbolAddress((void**)&cmh,  g_cmh);  cudaGetSymbolAddress((void**)&cml,  g_cml);
    cudaGetSymbolAddress((void**)&fmh,  g_fmh);  cudaGetSymbolAddress((void**)&fml,  g_fml);
    cudaGetSymbolAddress((void**)&cwmh, g_cwmh); cudaGetSymbolAddress((void**)&cwml, g_cwml);
    cudaGetSymbolAddress((void**)&fwmh, g_fwmh); cudaGetSymbolAddress((void**)&fwml, g_fwml);
    cudaGetSymbolAddress((void**)&wcch, g_wcch); cudaGetSymbolAddress((void**)&wccl, g_wccl);
    cudaGetSymbolAddress((void**)&wcfh, g_wcfh); cudaGetSymbolAddress((void**)&wcfl, g_wcfl);
    cudaGetSymbolAddress((void**)&wgh,  g_wgh);  cudaGetSymbolAddress((void**)&wgl,  g_wgl);
    cudaGetSymbolAddress((void**)&xh,   g_xh);   cudaGetSymbolAddress((void**)&xl,   g_xl);
    cudaGetSymbolAddress((void**)&rhh,  g_rhh);  cudaGetSymbolAddress((void**)&rhl,  g_rhl);
    cudaGetSymbolAddress((void**)&wph,  g_wph);  cudaGetSymbolAddress((void**)&wpl,  g_wpl);
    cudaGetSymbolAddress((void**)&wsh,  g_wsh);  cudaGetSymbolAddress((void**)&wsl,  g_wsl);

    cudaFuncSetAttribute(mma_gemm, cudaFuncAttributeMaxDynamicSharedMemorySize, GSMEM);
    cudaFuncSetAttribute(gemm_all, cudaFuncAttributeMaxDynamicSharedMemorySize, GSMEM);
    cudaFuncSetAttribute(step_qghmma, cudaFuncAttributeMaxDynamicSharedMemorySize, P_SMEM);

    // ---- prologue: 3 launches ----
    gather_all<<<2522, 256>>>(target, emb, latent, W_ih, hidden, cb_h, fb_h, b_hh);

    ConvJobs cj;
    long base = 0;
    auto setc = [&](int i, const float* src, int ld, int cs, int R, int K, int Rpad,
                    __nv_bfloat16* hi, __nv_bfloat16* lo) {
        cj.j[i] = ConvJob{src, ld, cs, R, K, Rpad, hi, lo, base};
        base += (long)Rpad * (K >> 3);
    };
    setc(0, c_memory, 512, 0, 1600, 512, 1664, cmh, cml);
    setc(1, f_memory, 512, 0, 1600, 512, 1664, fmh, fml);
    setc(2, W_pr, 512, 0, 32000, 512, 32000, wph, wpl);
    setc(3, cW_m, 512, 0, 512, 512, 512, cwmh, cwml);
    setc(4, fW_m, 512, 0, 512, 512, 512, fwmh, fwml);
    setc(5, W_ih, 1600, 512,  1536, 512, 1536, wcch, wccl);
    setc(6, W_ih, 1600, 1024, 1536, 512, 1536, wcfh, wcfl);
    setc(7, Wg, 576, 0, 1536, 576, 1536, wgh, wgl);
    setc(8, X, 576, 0, 960, 576, 1024, xh, xl);
    setc(9,  cW_h, 512, 0, 512, 512, 512, wsh,               wsl);
    setc(10, fW_h, 512, 0, 512, 512, 512, wsh + 512 * 512,   wsl + 512 * 512);
    setc(11, W_hh, 512, 0, 1536, 512, 1536, wsh + 1024 * 512, wsl + 1024 * 512);
    cj.total = base;
    conv_all<<<8192, 256>>>(cj);

    GemmJobs gj;
    gj.j[0] = GemmJob{cmh, cml, cwmh, cwml, 512, cb_m, kc, 1600, 512, 13, 0};
    gj.j[1] = GemmJob{fmh, fml, fwmh, fwml, 512, fb_m, kf, 1600, 512, 13, 52};
    gj.j[2] = GemmJob{cmh, cml, wcch, wccl, 512, nullptr, Pc, 1600, GDIM, 13, 104};
    gj.j[3] = GemmJob{fmh, fml, wcfh, wcfl, 512, nullptr, Pf, 1600, GDIM, 13, 260};
    gj.j[4] = GemmJob{xh, xl, wgh, wgl, 576, b_ih, gipre, 960, GDIM, 8, 416};
    gemm_all<<<512, 256, GSMEM>>>(gj);

    // ---- sequential decode: 2 launches per step ----
    for (int t = 0; t < T_STEPS; t++) {
        step_qghmma<<<20, 256, P_SMEM>>>();
        step_scoregate<<<dim3(4, BATCH), 256>>>(t, cW_o, cb_o, fW_o, fb_o, c_mask, f_mask);
    }

    // ---- deferred vocabulary projection ----
    conv_split<<<2048, 256>>>(reluh, 512, 0, 960, 512, 1024, rhh, rhl);
    mma_gemm<<<dim3(8, 250), 256, GSMEM>>>(rhh, rhl, wph, wpl, 512, b_pr, out, 960, VOCAB, 1);
}

// round 13
// speedup vs baseline: 1.2722x; 1.2722x over previous
#include <cuda_runtime.h>
#include <cuda_bf16.h>
#include <math.h>
#include <stdint.h>

// ---------------- problem constants ----------------
#define T_STEPS 30
#define BATCH   32
#define HID     512
#define S_LEN   50
#define VOCAB   32000
#define GDIM    1536   // 3*H
#define XK      576    // 512 emb + 64 latent

// ---------------- fp32 scratch ----------------
__device__ float g_kc[S_LEN * BATCH * HID];
__device__ float g_kf[S_LEN * BATCH * HID];
__device__ float g_Pc[S_LEN * BATCH * GDIM];
__device__ float g_Pf[S_LEN * BATCH * GDIM];
__device__ float g_X[T_STEPS * BATCH * XK];
__device__ float g_Wg[GDIM * XK];
__device__ float g_gipre[T_STEPS * BATCH * GDIM];
__device__ float g_qp[4][BATCH * 1024];      // K-split partials of [q]
__device__ float g_ghp[4][BATCH * GDIM];     // K-split partials of [gh]
__device__ float g_score[2 * S_LEN * BATCH];
__device__ float g_h[BATCH * HID];
__device__ float g_reluh[T_STEPS * BATCH * HID];
__device__ float g_bstack[2560];             // [cb_h | fb_h | b_hh]

// ---------------- bf16 split (hi/lo) row-major operand buffers ----------------
__device__ __nv_bfloat16 g_cmh[1664 * 512],  g_cml[1664 * 512];
__device__ __nv_bfloat16 g_fmh[1664 * 512],  g_fml[1664 * 512];
__device__ __nv_bfloat16 g_cwmh[512 * 512],  g_cwml[512 * 512];
__device__ __nv_bfloat16 g_fwmh[512 * 512],  g_fwml[512 * 512];
__device__ __nv_bfloat16 g_wcch[1536 * 512], g_wccl[1536 * 512];
__device__ __nv_bfloat16 g_wcfh[1536 * 512], g_wcfl[1536 * 512];
__device__ __nv_bfloat16 g_wgh[1536 * 576],  g_wgl[1536 * 576];
__device__ __nv_bfloat16 g_xh[1024 * 576],   g_xl[1024 * 576];
__device__ __nv_bfloat16 g_rhh[1024 * 512],  g_rhl[1024 * 512];
__device__ __nv_bfloat16 g_wph[32000 * 512], g_wpl[32000 * 512];
__device__ __nv_bfloat16 g_wsh[2560 * 512],  g_wsl[2560 * 512];   // stacked [cW_h; fW_h; W_hh]
__device__ __nv_bfloat16 g_hh[BATCH * 512],  g_hl[BATCH * 512];   // current h split

// ---------------- math helpers ----------------
__device__ __forceinline__ float tanhx(float x) {
    float e = __expf(2.0f * x);
    return 1.0f - __fdividef(2.0f, e + 1.0f);
}
__device__ __forceinline__ float sigx(float x) {
    return __fdividef(1.0f, 1.0f + __expf(-x));
}

// ---------------- PTX helpers (sm_80/sm_90-era, plain-sm_100-safe) ----------------
__device__ __forceinline__ uint32_t smem_u32(const void* p) {
    uint32_t a;
    asm("{ .reg .u64 t; cvta.to.shared.u64 t, %1; cvt.u32.u64 %0, t; }" : "=r"(a) : "l"(p));
    return a;
}
#define CP16(dst, src) asm volatile("cp.async.cg.shared.global [%0], [%1], 16;" :: "r"(dst), "l"(src))
#define CP_COMMIT()    asm volatile("cp.async.commit_group;")
#define CP_WAIT1()     asm volatile("cp.async.wait_group 1;")
#define CP_WAIT0()     asm volatile("cp.async.wait_group 0;")
#define CLUSTER_ARRIVE() asm volatile("barrier.cluster.arrive;" ::: "memory")
#define CLUSTER_WAIT()   asm volatile("barrier.cluster.wait;"   ::: "memory")

__device__ __forceinline__ void ldsm4(uint32_t* r, uint32_t addr) {
    asm volatile("ldmatrix.sync.aligned.m8n8.x4.shared.b16 {%0,%1,%2,%3}, [%4];"
        : "=r"(r[0]), "=r"(r[1]), "=r"(r[2]), "=r"(r[3]) : "r"(addr));
}
__device__ __forceinline__ void mma_bf16(float* d, const uint32_t* a, const uint32_t* b) {
    asm volatile("mma.sync.aligned.m16n8k16.row.col.f32.bf16.bf16.f32 "
        "{%0,%1,%2,%3}, {%4,%5,%6,%7}, {%8,%9}, {%0,%1,%2,%3};"
        : "+f"(d[0]), "+f"(d[1]), "+f"(d[2]), "+f"(d[3])
        : "r"(a[0]), "r"(a[1]), "r"(a[2]), "r"(a[3]), "r"(b[0]), "r"(b[1]));
}

__device__ __forceinline__ void split_bf16(float v, __nv_bfloat16& hi, __nv_bfloat16& lo) {
    hi = __float2bfloat16(v);
    lo = __float2bfloat16(v - __bfloat162float(hi));
}

// ---------------- fused gathers (X, Wg, h(+split), bstack) ----------------
__global__ void gather_all(const int* __restrict__ target,
                           const float* __restrict__ emb,
                           const float* __restrict__ latent,
                           const float* __restrict__ Wih,
                           const float* __restrict__ hidden,
                           const float* __restrict__ cbh,
                           const float* __restrict__ fbh,
                           const float* __restrict__ bhh)
{
    const int bx = blockIdx.x;
    if (bx < 960) {
        const int m = bx;
        const int t = m >> 5, b = m & 31;
        const int tok = (t == 0) ? 1 : target[(t - 1) * BATCH + b];
        float* xr = g_X + (size_t)m * XK;
        const float* er = emb + (size_t)tok * 512;
        for (int c = threadIdx.x; c < XK; c += blockDim.x)
            xr[c] = (c < 512) ? er[c] : latent[b * 64 + (c - 512)];
    } else if (bx < 2496) {
        const int n = bx - 960;
        float* wr = g_Wg + (size_t)n * XK;
        const float* src = Wih + (size_t)n * 1600;
        for (int c = threadIdx.x; c < XK; c += blockDim.x)
            wr[c] = (c < 512) ? src[c] : src[1536 + (c - 512)];
    } else if (bx < 2512) {
        const int i = (bx - 2496) * 256 + threadIdx.x;   // 4096 float4
        float4 v = ((const float4*)hidden)[i];
        ((float4*)g_h)[i] = v;
        __nv_bfloat16 h0, l0, h1, l1, h2, l2, h3, l3;
        split_bf16(v.x, h0, l0); split_bf16(v.y, h1, l1);
        split_bf16(v.z, h2, l2); split_bf16(v.w, h3, l3);
        const int e = i * 4;
        g_hh[e] = h0; g_hh[e + 1] = h1; g_hh[e + 2] = h2; g_hh[e + 3] = h3;
        g_hl[e] = l0; g_hl[e + 1] = l1; g_hl[e + 2] = l2; g_hl[e + 3] = l3;
    } else {
        const int r = (bx - 2512) * 256 + threadIdx.x;
        if (r < 2560) {
            float v;
            if (r < 512)       v = cbh[r];
            else if (r < 1024) v = fbh[r - 512];
            else               v = bhh[r - 1024];
            g_bstack[r] = v;
        }
    }
}

// ---------------- fused fp32 -> split-bf16 conversion (12 jobs, one launch) ----------------
struct ConvJob {
    const float* src;
    int ld, cs, R, K, Rpad;
    __nv_bfloat16 *hi, *lo;
    long base;      // granule prefix
};
struct ConvJobs { ConvJob j[12]; long total; };

__global__ void conv_all(ConvJobs jobs)
{
    for (long idx = (long)blockIdx.x * blockDim.x + threadIdx.x; idx < jobs.total;
         idx += (long)gridDim.x * blockDim.x) {
        int sidx = 11;
        #pragma unroll
        for (int s = 1; s < 12; s++)
            if (idx < jobs.j[s].base) { sidx = s - 1; break; }
        const ConvJob jb = jobs.j[sidx];
        const long local = idx - jb.base;
        const int gpr = jb.K >> 3;
        const int r = (int)(local / gpr);
        const int g = (int)(local - (long)r * gpr);
        float v[8];
        if (r < jb.R) {
            const float* p = jb.src + (size_t)r * jb.ld + jb.cs + g * 8;
            float4 u0 = *(const float4*)p;
            float4 u1 = *(const float4*)(p + 4);
            v[0] = u0.x; v[1] = u0.y; v[2] = u0.z; v[3] = u0.w;
            v[4] = u1.x; v[5] = u1.y; v[6] = u1.z; v[7] = u1.w;
        } else {
            #pragma unroll
            for (int k = 0; k < 8; k++) v[k] = 0.f;
        }
        __align__(16) unsigned short hb[8];
        __align__(16) unsigned short lb[8];
        #pragma unroll
        for (int k = 0; k < 8; k++) {
            __nv_bfloat16 h, l;
            split_bf16(v[k], h, l);
            hb[k] = reinterpret_cast<unsigned short&>(h);
            lb[k] = reinterpret_cast<unsigned short&>(l);
        }
        size_t o = (size_t)r * jb.K + (size_t)g * 8;
        *(uint4*)(jb.hi + o) = *(const uint4*)hb;
        *(uint4*)(jb.lo + o) = *(const uint4*)lb;
    }
}

// ---------------- HMMA split-bf16 NT GEMM tile (exact R4 body as device fn) ----------------
#define ROWB  144
#define TILEA (128 * ROWB)
#define STG   (2 * TILEA)
#define GSMEM (2 * STG)

__device__ __forceinline__ void gemm_tile(
    const __nv_bfloat16* __restrict__ Ah, const __nv_bfloat16* __restrict__ Al,
    const __nv_bfloat16* __restrict__ Bh, const __nv_bfloat16* __restrict__ Bl,
    int K, const float* __restrict__ bias, float* __restrict__ C,
    int Mreal, int Ncols, int outmode, int m0, int n0, char* sm)
{
    const int tid = threadIdx.x;
    const int nch = K >> 6;
    const int niter = 3 * nch;
    const uint32_t base = smem_u32(sm);

    const int lane = tid & 31, w = tid >> 5;
    const int wm = w & 3, wn = w >> 2;

    float acc[2][8][4];
    #pragma unroll
    for (int a = 0; a < 2; a++)
        #pragma unroll
        for (int b = 0; b < 8; b++)
            #pragma unroll
            for (int c = 0; c < 4; c++) acc[a][b][c] = 0.f;

    const int lr[4] = { (tid + 0) >> 3, (tid + 256) >> 3, (tid + 512) >> 3, (tid + 768) >> 3 };
    const int lg = tid & 7;

    auto load_stage = [&](int i, int stage) {
        const int p  = i / nch;
        const int kc = i - p * nch;
        const __nv_bfloat16* Ag = ((p == 1) ? Al : Ah) + (size_t)m0 * K + kc * 64;
        const __nv_bfloat16* Bg = ((p == 2) ? Bl : Bh) + (size_t)n0 * K + kc * 64;
        const uint32_t dA = base + stage * STG;
        const uint32_t dB = dA + TILEA;
        #pragma unroll
        for (int j = 0; j < 4; j++) {
            const int r = lr[j];
            CP16(dA + r * ROWB + lg * 16, Ag + (size_t)r * K + lg * 8);
            CP16(dB + r * ROWB + lg * 16, Bg + (size_t)r * K + lg * 8);
        }
        CP_COMMIT();
    };

    load_stage(0, 0);

    for (int i = 0; i < niter; i++) {
        const int cur = i & 1;
        if (i + 1 < niter) { load_stage(i + 1, cur ^ 1); CP_WAIT1(); }
        else               { CP_WAIT0(); }
        __syncthreads();

        const uint32_t sA = base + cur * STG;
        const uint32_t sB = sA + TILEA;
        const uint32_t aBase = sA + (uint32_t)(wm * 32 + (lane & 15)) * ROWB + (uint32_t)(lane >> 4) * 16;
        const uint32_t bBase = sB + (uint32_t)(wn * 64 + (lane & 7) + ((lane >> 4) << 3)) * ROWB
                                  + (uint32_t)(((lane >> 3) & 1) << 4);

        #pragma unroll
        for (int ks = 0; ks < 4; ks++) {
            uint32_t af[2][4], bfr[4][4];
            ldsm4(af[0], aBase + ks * 32);
            ldsm4(af[1], aBase + 16 * ROWB + ks * 32);
            #pragma unroll
            for (int ni = 0; ni < 4; ni++)
                ldsm4(bfr[ni], bBase + ni * 16 * ROWB + ks * 32);
            #pragma unroll
            for (int mi = 0; mi < 2; mi++)
                #pragma unroll
                for (int ni = 0; ni < 4; ni++) {
                    mma_bf16(acc[mi][2 * ni],     af[mi], &bfr[ni][0]);
                    mma_bf16(acc[mi][2 * ni + 1], af[mi], &bfr[ni][2]);
                }
        }
        __syncthreads();
    }

    const int ncol0 = n0 + wn * 64 + (lane & 3) * 2;
    #pragma unroll
    for (int mi = 0; mi < 2; mi++) {
        const int ml = wm * 32 + mi * 16 + (lane >> 2);
        #pragma unroll
        for (int half = 0; half < 2; half++) {
            const int m = m0 + ml + half * 8;
            if (m >= Mreal) continue;
            size_t orow = outmode ? ((size_t)(m & 31) * T_STEPS + (m >> 5)) : (size_t)m;
            float* cr = C + orow * Ncols + ncol0;
            #pragma unroll
            for (int nj = 0; nj < 8; nj++) {
                const int c = ncol0 + nj * 8;
                float b0 = bias ? bias[c] : 0.f;
                float b1 = bias ? bias[c + 1] : 0.f;
                float2 v;
                v.x = acc[mi][nj][half * 2 + 0] + b0;
                v.y = acc[mi][nj][half * 2 + 1] + b1;
                *(float2*)(cr + nj * 8) = v;
            }
        }
    }
}

// single-job GEMM (projection)
__global__ void __launch_bounds__(256) mma_gemm(
    const __nv_bfloat16* __restrict__ Ah, const __nv_bfloat16* __restrict__ Al,
    const __nv_bfloat16* __restrict__ Bh, const __nv_bfloat16* __restrict__ Bl,
    int K, const float* __restrict__ bias, float* __restrict__ C,
    int Mreal, int Ncols, int outmode)
{
    extern __shared__ __align__(128) char sm[];
    gemm_tile(Ah, Al, Bh, Bl, K, bias, C, Mreal, Ncols, outmode,
              blockIdx.x * 128, blockIdx.y * 128, sm);
}

// all 5 precompute GEMMs in one launch (block-range dispatch)
struct GemmJob {
    const __nv_bfloat16 *Ah, *Al, *Bh, *Bl;
    int K;
    const float* bias;
    float* C;
    int Mreal, Ncols, mw, base;
};
struct GemmJobs { GemmJob j[5]; };

__global__ void __launch_bounds__(256) gemm_all(GemmJobs jobs)
{
    extern __shared__ __align__(128) char sm[];
    const int bx = blockIdx.x;
    int s = 4;
    #pragma unroll
    for (int k = 1; k < 5; k++)
        if (bx < jobs.j[k].base) { s = k - 1; break; }
    const GemmJob jb = jobs.j[s];
    const int i = bx - jb.base;
    const int m0 = (i % jb.mw) * 128;
    const int n0 = (i / jb.mw) * 128;
    gemm_tile(jb.Ah, jb.Al, jb.Bh, jb.Bl, jb.K, jb.bias, jb.C,
              jb.Mreal, jb.Ncols, 0, m0, n0, sm);
}

// ---------------- decode step A via HMMA, K-split x4 ----------------
// grid 80 = (20 col-tiles x 4 K-quarters) x 256 threads.
// Block (nt, ks): partial [q|gh] rows nt*128..+128 over K range [ks*128, +128).
// 6 pipeline stages (3 passes x 2 chunks). Partials into g_qp[ks] / g_ghp[ks].
#define P_AROW 4608              // 32 * 144
#define P_STG  23040             // (32 + 128) * 144
#define P_SMEM (2 * P_STG)       // 46080

__global__ void __launch_bounds__(256) step_qghmma()
{
    extern __shared__ __align__(128) char psm[];
    const uint32_t base = smem_u32(psm);
    const int tid = threadIdx.x;
    const int lane = tid & 31;
    const int w = tid >> 5;
    const int nt = blockIdx.x % 20;
    const int ksp = blockIdx.x / 20;     // 0..3
    const int n0 = nt * 128;

    float acc[2][2][4];
    #pragma unroll
    for (int a = 0; a < 2; a++)
        #pragma unroll
        for (int b = 0; b < 2; b++)
            #pragma unroll
            for (int c = 0; c < 4; c++) acc[a][b][c] = 0.f;

    const int arow = tid >> 3;           // 0..31 (batch)
    const int lg = tid & 7;

    auto load_stage = [&](int i, int stage) {
        const int p  = i >> 1;           // pass: 0 Ah*Bh, 1 Al*Bh, 2 Ah*Bl
        const int kc = ksp * 2 + (i & 1);
        const __nv_bfloat16* Ag = ((p == 1) ? g_hl : g_hh)
            + ((size_t)arow * 512 + kc * 64 + lg * 8);
        const __nv_bfloat16* Bbase = (p == 2) ? g_wsl : g_wsh;
        const uint32_t dA = base + stage * P_STG;
        const uint32_t dB = dA + P_AROW;
        CP16(dA + arow * ROWB + lg * 16, Ag);
        #pragma unroll
        for (int j = 0; j < 4; j++) {
            const int r = arow + 32 * j;
            CP16(dB + r * ROWB + lg * 16,
                 Bbase + ((size_t)(n0 + r) * 512 + kc * 64 + lg * 8));
        }
        CP_COMMIT();
    };

    load_stage(0, 0);

    for (int i = 0; i < 6; i++) {
        const int cur = i & 1;
        if (i + 1 < 6) { load_stage(i + 1, cur ^ 1); CP_WAIT1(); }
        else           { CP_WAIT0(); }
        __syncthreads();

        const uint32_t sA = base + cur * P_STG;
        const uint32_t sB = sA + P_AROW;
        const uint32_t aBase = sA + (uint32_t)(lane & 15) * ROWB + (uint32_t)(lane >> 4) * 16;
        const uint32_t bBase = sB + (uint32_t)(w * 16 + (lane & 7) + ((lane >> 4) << 3)) * ROWB
                                  + (uint32_t)(((lane >> 3) & 1) << 4);

        #pragma unroll
        for (int ks = 0; ks < 4; ks++) {
            uint32_t af0[4], af1[4], bfr[4];
            ldsm4(af0, aBase + ks * 32);
            ldsm4(af1, aBase + 16 * ROWB + ks * 32);
            ldsm4(bfr, bBase + ks * 32);
            mma_bf16(acc[0][0], af0, &bfr[0]);
            mma_bf16(acc[0][1], af0, &bfr[2]);
            mma_bf16(acc[1][0], af1, &bfr[0]);
            mma_bf16(acc[1][1], af1, &bfr[2]);
        }
        __syncthreads();
    }

    float* qp  = g_qp[ksp];
    float* ghp = g_ghp[ksp];
    const int ncol0 = n0 + w * 16 + (lane & 3) * 2;
    #pragma unroll
    for (int mi = 0; mi < 2; mi++) {
        #pragma unroll
        for (int half = 0; half < 2; half++) {
            const int b = mi * 16 + (lane >> 2) + half * 8;    // batch 0..31
            #pragma unroll
            for (int nj = 0; nj < 2; nj++) {
                #pragma unroll
                for (int e = 0; e < 2; e++) {
                    const int c = ncol0 + nj * 8 + e;          // stacked row
                    float v = acc[mi][nj][half * 2 + e];
                    if (ksp == 0) v += g_bstack[c];
                    if (c < 1024) qp[b * 1024 + c] = v;
                    else          ghp[(size_t)b * GDIM + (c - 1024)] = v;
                }
            }
        }
    }
}

// ---------------- fused decode step B+C (R11) + partial-sum consumption ----------------
__global__ void __cluster_dims__(4, 1, 1) __launch_bounds__(256) step_scoregate(
    int tstep,
    const float* __restrict__ cWo, const float* __restrict__ cbo,
    const float* __restrict__ fWo, const float* __restrict__ fbo,
    const int* __restrict__ cmask, const int* __restrict__ fmask)
{
    __shared__ __align__(16) float sq[1024];
    __shared__ float s_all[100];
    __shared__ float attn[2][S_LEN];
    __shared__ float s_ps[384];

    const int qd = blockIdx.x;
    const int b  = blockIdx.y;
    const int tid = threadIdx.x;
    const int lane = tid & 31;
    const int w = tid >> 5;

    // sum the 4 q partials for this batch into smem
    for (int i = tid; i < 1024; i += 256)
        sq[i] = g_qp[0][b * 1024 + i] + g_qp[1][b * 1024 + i]
              + g_qp[2][b * 1024 + i] + g_qp[3][b * 1024 + i];
    __syncthreads();

    for (int ui = w; ui < 25; ui += 8) {
        const int u = qd * 25 + ui;
        const int a = u / S_LEN;
        const int s = u % S_LEN;
        const float* kr = (a ? g_kf : g_kc) + (size_t)(s * BATCH + b) * HID;
        const float* qr = sq + a * 512;
        const float* Wo = a ? fWo : cWo;
        float sacc = 0.f;
        #pragma unroll
        for (int j = 0; j < 4; j++) {
            float4 kv = *(const float4*)(kr + j * 128 + lane * 4);
            float4 qv = *(const float4*)(qr + j * 128 + lane * 4);
            float4 wv = *(const float4*)(Wo + j * 128 + lane * 4);
            sacc = fmaf(wv.x, tanhx(qv.x + kv.x), sacc);
            sacc = fmaf(wv.y, tanhx(qv.y + kv.y), sacc);
            sacc = fmaf(wv.z, tanhx(qv.z + kv.z), sacc);
            sacc = fmaf(wv.w, tanhx(qv.w + kv.w), sacc);
        }
        #pragma unroll
        for (int o = 16; o; o >>= 1) sacc += __shfl_xor_sync(0xffffffffu, sacc, o);
        if (lane == 0) {
            const int* msk = a ? fmask : cmask;
            float v = sacc + (a ? fbo : cbo)[0];
            if (msk[s * BATCH + b] == 0) v = -INFINITY;
            __stcg(&g_score[(a * S_LEN + s) * BATCH + b], v);
        }
    }

    CLUSTER_ARRIVE();
    CLUSTER_WAIT();

    if (tid < 100) s_all[tid] = __ldcg(&g_score[tid * BATCH + b]);
    __syncthreads();

    if (w < 2) {
        const int a = w;
        float v0 = s_all[a * S_LEN + lane];
        float v1 = (lane < S_LEN - 32) ? s_all[a * S_LEN + 32 + lane] : -INFINITY;
        float mx = fmaxf(v0, v1);
        #pragma unroll
        for (int o = 16; o; o >>= 1) mx = fmaxf(mx, __shfl_xor_sync(0xffffffffu, mx, o));
        float e0 = __expf(v0 - mx);
        float e1 = (lane < S_LEN - 32) ? __expf(v1 - mx) : 0.f;
        float sm = e0 + e1;
        #pragma unroll
        for (int o = 16; o; o >>= 1) sm += __shfl_xor_sync(0xffffffffu, sm, o);
        float inv = __fdividef(1.f, sm);
        attn[a][lane] = e0 * inv;
        if (lane < S_LEN - 32) attn[a][32 + lane] = e1 * inv;
    }
    __syncthreads();

    const int j = qd * 128 + (tid & 127);
    const int shalf = tid >> 7;
    float gr = 0.f, gz = 0.f, gn = 0.f;
    const int sbeg = shalf * 25;
    #pragma unroll 1
    for (int s = sbeg; s < sbeg + 25; s++) {
        const float ac = attn[0][s];
        const float af = attn[1][s];
        const float* pc = g_Pc + (size_t)(s * BATCH + b) * GDIM;
        const float* pf = g_Pf + (size_t)(s * BATCH + b) * GDIM;
        gr = fmaf(ac, pc[j],        gr); gr = fmaf(af, pf[j],        gr);
        gz = fmaf(ac, pc[512 + j],  gz); gz = fmaf(af, pf[512 + j],  gz);
        gn = fmaf(ac, pc[1024 + j], gn); gn = fmaf(af, pf[1024 + j], gn);
    }
    if (shalf == 1) {
        s_ps[tid & 127]         = gr;
        s_ps[128 + (tid & 127)] = gz;
        s_ps[256 + (tid & 127)] = gn;
    }
    __syncthreads();
    if (shalf == 0) {
        gr += s_ps[tid];
        gz += s_ps[128 + tid];
        gn += s_ps[256 + tid];
        const float* gip = g_gipre + (size_t)(tstep * BATCH + b) * GDIM;
        const size_t gb = (size_t)b * GDIM;
        const float ghr = g_ghp[0][gb + j]        + g_ghp[1][gb + j]
                        + g_ghp[2][gb + j]        + g_ghp[3][gb + j];
        const float ghz = g_ghp[0][gb + 512 + j]  + g_ghp[1][gb + 512 + j]
                        + g_ghp[2][gb + 512 + j]  + g_ghp[3][gb + 512 + j];
        const float ghn = g_ghp[0][gb + 1024 + j] + g_ghp[1][gb + 1024 + j]
                        + g_ghp[2][gb + 1024 + j] + g_ghp[3][gb + 1024 + j];
        const float gir = gip[j]        + gr;
        const float giz = gip[512 + j]  + gz;
        const float gin = gip[1024 + j] + gn;
        const float r = sigx(gir + ghr);
        const float z = sigx(giz + ghz);
        const float n = tanhx(gin + r * ghn);
        const float hv = g_h[b * HID + j];
        const float hn = (1.f - z) * n + z * hv;
        g_h[b * HID + j] = hn;
        g_reluh[(size_t)(tstep * BATCH + b) * HID + j] = fmaxf(hn, 0.f);
        __nv_bfloat16 hi, lo;
        split_bf16(hn, hi, lo);
        g_hh[b * 512 + j] = hi;
        g_hl[b * 512 + j] = lo;
    }
}

// single-job conv (reluh, after loop)
__global__ void conv_split(const float* __restrict__ src, int ld, int colstart,
                           int R, int K, int Rpad,
                           __nv_bfloat16* __restrict__ hi, __nv_bfloat16* __restrict__ lo)
{
    const int gpr = K >> 3;
    const long total = (long)Rpad * gpr;
    for (long idx = (long)blockIdx.x * blockDim.x + threadIdx.x; idx < total;
         idx += (long)gridDim.x * blockDim.x) {
        int r = (int)(idx / gpr);
        int g = (int)(idx - (long)r * gpr);
        float v[8];
        if (r < R) {
            const float* p = src + (size_t)r * ld + colstart + g * 8;
            float4 u0 = *(const float4*)p;
            float4 u1 = *(const float4*)(p + 4);
            v[0] = u0.x; v[1] = u0.y; v[2] = u0.z; v[3] = u0.w;
            v[4] = u1.x; v[5] = u1.y; v[6] = u1.z; v[7] = u1.w;
        } else {
            #pragma unroll
            for (int j = 0; j < 8; j++) v[j] = 0.f;
        }
        __align__(16) unsigned short hb[8];
        __align__(16) unsigned short lb[8];
        #pragma unroll
        for (int j = 0; j < 8; j++) {
            __nv_bfloat16 h, l;
            split_bf16(v[j], h, l);
            hb[j] = reinterpret_cast<unsigned short&>(h);
            lb[j] = reinterpret_cast<unsigned short&>(l);
        }
        size_t o = (size_t)r * K + (size_t)g * 8;
        *(uint4*)(hi + o) = *(const uint4*)hb;
        *(uint4*)(lo + o) = *(const uint4*)lb;
    }
}

// ---------------- launcher ----------------
extern "C" void kernel_launch(void* const* d_in, const int* in_sizes, int n_in,
                              void* d_out, int out_size)
{
    (void)in_sizes; (void)n_in; (void)out_size;

    const float* c_memory = (const float*)d_in[0];
    const int*   c_mask   = (const int*)  d_in[1];
    const float* f_memory = (const float*)d_in[2];
    const int*   f_mask   = (const int*)  d_in[3];
    const float* hidden   = (const float*)d_in[4];
    const float* latent   = (const float*)d_in[6];
    const int*   target   = (const int*)  d_in[7];
    const float* emb      = (const float*)d_in[8];
    const float* cW_h = (const float*)d_in[9];
    const float* cb_h = (const float*)d_in[10];
    const float* cW_m = (const float*)d_in[11];
    const float* cb_m = (const float*)d_in[12];
    const float* cW_o = (const float*)d_in[13];
    const float* cb_o = (const float*)d_in[14];
    const float* fW_h = (const float*)d_in[15];
    const float* fb_h = (const float*)d_in[16];
    const float* fW_m = (const float*)d_in[17];
    const float* fb_m = (const float*)d_in[18];
    const float* fW_o = (const float*)d_in[19];
    const float* fb_o = (const float*)d_in[20];
    const float* W_ih = (const float*)d_in[21];
    const float* b_ih = (const float*)d_in[22];
    const float* W_hh = (const float*)d_in[23];
    const float* b_hh = (const float*)d_in[24];
    const float* W_pr = (const float*)d_in[25];
    const float* b_pr = (const float*)d_in[26];
    float* out = (float*)d_out;

    float *kc, *kf, *Pc, *Pf, *X, *Wg, *gipre, *reluh;
    cudaGetSymbolAddress((void**)&kc,    g_kc);
    cudaGetSymbolAddress((void**)&kf,    g_kf);
    cudaGetSymbolAddress((void**)&Pc,    g_Pc);
    cudaGetSymbolAddress((void**)&Pf,    g_Pf);
    cudaGetSymbolAddress((void**)&X,     g_X);
    cudaGetSymbolAddress((void**)&Wg,    g_Wg);
    cudaGetSymbolAddress((void**)&gipre, g_gipre);
    cudaGetSymbolAddress((void**)&reluh, g_reluh);

    __nv_bfloat16 *cmh, *cml, *fmh, *fml, *cwmh, *cwml, *fwmh, *fwml;
    __nv_bfloat16 *wcch, *wccl, *wcfh, *wcfl, *wgh, *wgl, *xh, *xl, *rhh, *rhl, *wph, *wpl;
    __nv_bfloat16 *wsh, *wsl;
    cudaGetSymbolAddress((void**)&cmh,  g_cmh);  cudaGetSymbolAddress((void**)&cml,  g_cml);
    cudaGetSymbolAddress((void**)&fmh,  g_fmh);  cudaGetSymbolAddress((void**)&fml,  g_fml);
    cudaGetSymbolAddress((void**)&cwmh, g_cwmh); cudaGetSymbolAddress((void**)&cwml, g_cwml);
    cudaGetSymbolAddress((void**)&fwmh, g_fwmh); cudaGetSymbolAddress((void**)&fwml, g_fwml);
    cudaGetSymbolAddress((void**)&wcch, g_wcch); cudaGetSymbolAddress((void**)&wccl, g_wccl);
    cudaGetSymbolAddress((void**)&wcfh, g_wcfh); cudaGetSymbolAddress((void**)&wcfl, g_wcfl);
    cudaGetSymbolAddress((void**)&wgh,  g_wgh);  cudaGetSymbolAddress((void**)&wgl,  g_wgl);
    cudaGetSymbolAddress((void**)&xh,   g_xh);   cudaGetSymbolAddress((void**)&xl,   g_xl);
    cudaGetSymbolAddress((void**)&rhh,  g_rhh);  cudaGetSymbolAddress((void**)&rhl,  g_rhl);
    cudaGetSymbolAddress((void**)&wph,  g_wph);  cudaGetSymbolAddress((void**)&wpl,  g_wpl);
    cudaGetSymbolAddress((void**)&wsh,  g_wsh);  cudaGetSymbolAddress((void**)&wsl,  g_wsl);

    cudaFuncSetAttribute(mma_gemm, cudaFuncAttributeMaxDynamicSharedMemorySize, GSMEM);
    cudaFuncSetAttribute(gemm_all, cudaFuncAttributeMaxDynamicSharedMemorySize, GSMEM);
    cudaFuncSetAttribute(step_qghmma, cudaFuncAttributeMaxDynamicSharedMemorySize, P_SMEM);

    // ---- prologue: 3 launches ----
    gather_all<<<2522, 256>>>(target, emb, latent, W_ih, hidden, cb_h, fb_h, b_hh);

    ConvJobs cj;
    long base = 0;
    auto setc = [&](int i, const float* src, int ld, int cs, int R, int K, int Rpad,
                    __nv_bfloat16* hi, __nv_bfloat16* lo) {
        cj.j[i] = ConvJob{src, ld, cs, R, K, Rpad, hi, lo, base};
        base += (long)Rpad * (K >> 3);
    };
    setc(0, c_memory, 512, 0, 1600, 512, 1664, cmh, cml);
    setc(1, f_memory, 512, 0, 1600, 512, 1664, fmh, fml);
    setc(2, W_pr, 512, 0, 32000, 512, 32000, wph, wpl);
    setc(3, cW_m, 512, 0, 512, 512, 512, cwmh, cwml);
    setc(4, fW_m, 512, 0, 512, 512, 512, fwmh, fwml);
    setc(5, W_ih, 1600, 512,  1536, 512, 1536, wcch, wccl);
    setc(6, W_ih, 1600, 1024, 1536, 512, 1536, wcfh, wcfl);
    setc(7, Wg, 576, 0, 1536, 576, 1536, wgh, wgl);
    setc(8, X, 576, 0, 960, 576, 1024, xh, xl);
    setc(9,  cW_h, 512, 0, 512, 512, 512, wsh,               wsl);
    setc(10, fW_h, 512, 0, 512, 512, 512, wsh + 512 * 512,   wsl + 512 * 512);
    setc(11, W_hh, 512, 0, 1536, 512, 1536, wsh + 1024 * 512, wsl + 1024 * 512);
    cj.total = base;
    conv_all<<<8192, 256>>>(cj);

    GemmJobs gj;
    gj.j[0] = GemmJob{cmh, cml, cwmh, cwml, 512, cb_m, kc, 1600, 512, 13, 0};
    gj.j[1] = GemmJob{fmh, fml, fwmh, fwml, 512, fb_m, kf, 1600, 512, 13, 52};
    gj.j[2] = GemmJob{cmh, cml, wcch, wccl, 512, nullptr, Pc, 1600, GDIM, 13, 104};
    gj.j[3] = GemmJob{fmh, fml, wcfh, wcfl, 512, nullptr, Pf, 1600, GDIM, 13, 260};
    gj.j[4] = GemmJob{xh, xl, wgh, wgl, 576, b_ih, gipre, 960, GDIM, 8, 416};
    gemm_all<<<512, 256, GSMEM>>>(gj);

    // ---- sequential decode: 2 launches per step ----
    for (int t = 0; t < T_STEPS; t++) {
        step_qghmma<<<80, 256, P_SMEM>>>();
        step_scoregate<<<dim3(4, BATCH), 256>>>(t, cW_o, cb_o, fW_o, fb_o, c_mask, f_mask);
    }

    // ---- deferred vocabulary projection ----
    conv_split<<<2048, 256>>>(reluh, 512, 0, 960, 512, 1024, rhh, rhl);
    mma_gemm<<<dim3(8, 250), 256, GSMEM>>>(rhh, rhl, wph, wpl, 512, b_pr, out, 960, VOCAB, 1);
}

// round 14
// speedup vs baseline: 1.3061x; 1.0266x over previous
#include <cuda_runtime.h>
#include <cuda_bf16.h>
#include <math.h>
#include <stdint.h>

// ---------------- problem constants ----------------
#define T_STEPS 30
#define BATCH   32
#define HID     512
#define S_LEN   50
#define VOCAB   32000
#define GDIM    1536   // 3*H
#define XK      576    // 512 emb + 64 latent

// ---------------- fp32 scratch ----------------
__device__ float g_kc[S_LEN * BATCH * HID];
__device__ float g_kf[S_LEN * BATCH * HID];
__device__ float g_Pc[S_LEN * BATCH * GDIM];
__device__ float g_Pf[S_LEN * BATCH * GDIM];
__device__ float g_X[T_STEPS * BATCH * XK];
__device__ float g_Wg[GDIM * XK];
__device__ float g_gipre[T_STEPS * BATCH * GDIM];
__device__ float g_qp[4][BATCH * 1024];      // K-split partials of [q]
__device__ float g_ghp[4][BATCH * GDIM];     // K-split partials of [gh]
__device__ float g_score[2 * S_LEN * BATCH];
__device__ float g_h[BATCH * HID];
__device__ float g_reluh[T_STEPS * BATCH * HID];
__device__ float g_bstack[2560];             // [cb_h | fb_h | b_hh]

// ---------------- bf16 split (hi/lo) row-major operand buffers ----------------
__device__ __nv_bfloat16 g_cmh[1664 * 512],  g_cml[1664 * 512];
__device__ __nv_bfloat16 g_fmh[1664 * 512],  g_fml[1664 * 512];
__device__ __nv_bfloat16 g_cwmh[512 * 512],  g_cwml[512 * 512];
__device__ __nv_bfloat16 g_fwmh[512 * 512],  g_fwml[512 * 512];
__device__ __nv_bfloat16 g_wcch[1536 * 512], g_wccl[1536 * 512];
__device__ __nv_bfloat16 g_wcfh[1536 * 512], g_wcfl[1536 * 512];
__device__ __nv_bfloat16 g_wgh[1536 * 576],  g_wgl[1536 * 576];
__device__ __nv_bfloat16 g_xh[1024 * 576],   g_xl[1024 * 576];
__device__ __nv_bfloat16 g_rhh[1024 * 512],  g_rhl[1024 * 512];
__device__ __nv_bfloat16 g_wph[32000 * 512], g_wpl[32000 * 512];
__device__ __nv_bfloat16 g_wsh[2560 * 512],  g_wsl[2560 * 512];   // stacked [cW_h; fW_h; W_hh]
__device__ __nv_bfloat16 g_hh[BATCH * 512],  g_hl[BATCH * 512];   // current h split

// ---------------- math helpers ----------------
__device__ __forceinline__ float tanhx(float x) {
    float e = __expf(2.0f * x);
    return 1.0f - __fdividef(2.0f, e + 1.0f);
}
__device__ __forceinline__ float sigx(float x) {
    return __fdividef(1.0f, 1.0f + __expf(-x));
}

// ---------------- PTX helpers (sm_80/sm_90-era, plain-sm_100-safe) ----------------
__device__ __forceinline__ uint32_t smem_u32(const void* p) {
    uint32_t a;
    asm("{ .reg .u64 t; cvta.to.shared.u64 t, %1; cvt.u32.u64 %0, t; }" : "=r"(a) : "l"(p));
    return a;
}
#define CP16(dst, src) asm volatile("cp.async.cg.shared.global [%0], [%1], 16;" :: "r"(dst), "l"(src))
#define CP_COMMIT()    asm volatile("cp.async.commit_group;")
#define CP_WAIT1()     asm volatile("cp.async.wait_group 1;")
#define CP_WAIT0()     asm volatile("cp.async.wait_group 0;")
#define CLUSTER_ARRIVE() asm volatile("barrier.cluster.arrive;" ::: "memory")
#define CLUSTER_WAIT()   asm volatile("barrier.cluster.wait;"   ::: "memory")

template <int N>
__device__ __forceinline__ void cp_waitn() {
    asm volatile("cp.async.wait_group %0;" :: "n"(N));
}

__device__ __forceinline__ void ldsm4(uint32_t* r, uint32_t addr) {
    asm volatile("ldmatrix.sync.aligned.m8n8.x4.shared.b16 {%0,%1,%2,%3}, [%4];"
        : "=r"(r[0]), "=r"(r[1]), "=r"(r[2]), "=r"(r[3]) : "r"(addr));
}
__device__ __forceinline__ void mma_bf16(float* d, const uint32_t* a, const uint32_t* b) {
    asm volatile("mma.sync.aligned.m16n8k16.row.col.f32.bf16.bf16.f32 "
        "{%0,%1,%2,%3}, {%4,%5,%6,%7}, {%8,%9}, {%0,%1,%2,%3};"
        : "+f"(d[0]), "+f"(d[1]), "+f"(d[2]), "+f"(d[3])
        : "r"(a[0]), "r"(a[1]), "r"(a[2]), "r"(a[3]), "r"(b[0]), "r"(b[1]));
}

__device__ __forceinline__ void split_bf16(float v, __nv_bfloat16& hi, __nv_bfloat16& lo) {
    hi = __float2bfloat16(v);
    lo = __float2bfloat16(v - __bfloat162float(hi));
}

// ---------------- fused gathers (X, Wg, h(+split), bstack) ----------------
__global__ void gather_all(const int* __restrict__ target,
                           const float* __restrict__ emb,
                           const float* __restrict__ latent,
                           const float* __restrict__ Wih,
                           const float* __restrict__ hidden,
                           const float* __restrict__ cbh,
                           const float* __restrict__ fbh,
                           const float* __restrict__ bhh)
{
    const int bx = blockIdx.x;
    if (bx < 960) {
        const int m = bx;
        const int t = m >> 5, b = m & 31;
        const int tok = (t == 0) ? 1 : target[(t - 1) * BATCH + b];
        float* xr = g_X + (size_t)m * XK;
        const float* er = emb + (size_t)tok * 512;
        for (int c = threadIdx.x; c < XK; c += blockDim.x)
            xr[c] = (c < 512) ? er[c] : latent[b * 64 + (c - 512)];
    } else if (bx < 2496) {
        const int n = bx - 960;
        float* wr = g_Wg + (size_t)n * XK;
        const float* src = Wih + (size_t)n * 1600;
        for (int c = threadIdx.x; c < XK; c += blockDim.x)
            wr[c] = (c < 512) ? src[c] : src[1536 + (c - 512)];
    } else if (bx < 2512) {
        const int i = (bx - 2496) * 256 + threadIdx.x;   // 4096 float4
        float4 v = ((const float4*)hidden)[i];
        ((float4*)g_h)[i] = v;
        __nv_bfloat16 h0, l0, h1, l1, h2, l2, h3, l3;
        split_bf16(v.x, h0, l0); split_bf16(v.y, h1, l1);
        split_bf16(v.z, h2, l2); split_bf16(v.w, h3, l3);
        const int e = i * 4;
        g_hh[e] = h0; g_hh[e + 1] = h1; g_hh[e + 2] = h2; g_hh[e + 3] = h3;
        g_hl[e] = l0; g_hl[e + 1] = l1; g_hl[e + 2] = l2; g_hl[e + 3] = l3;
    } else {
        const int r = (bx - 2512) * 256 + threadIdx.x;
        if (r < 2560) {
            float v;
            if (r < 512)       v = cbh[r];
            else if (r < 1024) v = fbh[r - 512];
            else               v = bhh[r - 1024];
            g_bstack[r] = v;
        }
    }
}

// ---------------- fused fp32 -> split-bf16 conversion (12 jobs, one launch) ----------------
struct ConvJob {
    const float* src;
    int ld, cs, R, K, Rpad;
    __nv_bfloat16 *hi, *lo;
    long base;      // granule prefix
};
struct ConvJobs { ConvJob j[12]; long total; };

__global__ void conv_all(ConvJobs jobs)
{
    for (long idx = (long)blockIdx.x * blockDim.x + threadIdx.x; idx < jobs.total;
         idx += (long)gridDim.x * blockDim.x) {
        int sidx = 11;
        #pragma unroll
        for (int s = 1; s < 12; s++)
            if (idx < jobs.j[s].base) { sidx = s - 1; break; }
        const ConvJob jb = jobs.j[sidx];
        const long local = idx - jb.base;
        const int gpr = jb.K >> 3;
        const int r = (int)(local / gpr);
        const int g = (int)(local - (long)r * gpr);
        float v[8];
        if (r < jb.R) {
            const float* p = jb.src + (size_t)r * jb.ld + jb.cs + g * 8;
            float4 u0 = *(const float4*)p;
            float4 u1 = *(const float4*)(p + 4);
            v[0] = u0.x; v[1] = u0.y; v[2] = u0.z; v[3] = u0.w;
            v[4] = u1.x; v[5] = u1.y; v[6] = u1.z; v[7] = u1.w;
        } else {
            #pragma unroll
            for (int k = 0; k < 8; k++) v[k] = 0.f;
        }
        __align__(16) unsigned short hb[8];
        __align__(16) unsigned short lb[8];
        #pragma unroll
        for (int k = 0; k < 8; k++) {
            __nv_bfloat16 h, l;
            split_bf16(v[k], h, l);
            hb[k] = reinterpret_cast<unsigned short&>(h);
            lb[k] = reinterpret_cast<unsigned short&>(l);
        }
        size_t o = (size_t)r * jb.K + (size_t)g * 8;
        *(uint4*)(jb.hi + o) = *(const uint4*)hb;
        *(uint4*)(jb.lo + o) = *(const uint4*)lb;
    }
}

// ---------------- HMMA split-bf16 NT GEMM tile (exact R4 body as device fn) ----------------
#define ROWB  144
#define TILEA (128 * ROWB)
#define STG   (2 * TILEA)
#define GSMEM (2 * STG)

__device__ __forceinline__ void gemm_tile(
    const __nv_bfloat16* __restrict__ Ah, const __nv_bfloat16* __restrict__ Al,
    const __nv_bfloat16* __restrict__ Bh, const __nv_bfloat16* __restrict__ Bl,
    int K, const float* __restrict__ bias, float* __restrict__ C,
    int Mreal, int Ncols, int outmode, int m0, int n0, char* sm)
{
    const int tid = threadIdx.x;
    const int nch = K >> 6;
    const int niter = 3 * nch;
    const uint32_t base = smem_u32(sm);

    const int lane = tid & 31, w = tid >> 5;
    const int wm = w & 3, wn = w >> 2;

    float acc[2][8][4];
    #pragma unroll
    for (int a = 0; a < 2; a++)
        #pragma unroll
        for (int b = 0; b < 8; b++)
            #pragma unroll
            for (int c = 0; c < 4; c++) acc[a][b][c] = 0.f;

    const int lr[4] = { (tid + 0) >> 3, (tid + 256) >> 3, (tid + 512) >> 3, (tid + 768) >> 3 };
    const int lg = tid & 7;

    auto load_stage = [&](int i, int stage) {
        const int p  = i / nch;
        const int kc = i - p * nch;
        const __nv_bfloat16* Ag = ((p == 1) ? Al : Ah) + (size_t)m0 * K + kc * 64;
        const __nv_bfloat16* Bg = ((p == 2) ? Bl : Bh) + (size_t)n0 * K + kc * 64;
        const uint32_t dA = base + stage * STG;
        const uint32_t dB = dA + TILEA;
        #pragma unroll
        for (int j = 0; j < 4; j++) {
            const int r = lr[j];
            CP16(dA + r * ROWB + lg * 16, Ag + (size_t)r * K + lg * 8);
            CP16(dB + r * ROWB + lg * 16, Bg + (size_t)r * K + lg * 8);
        }
        CP_COMMIT();
    };

    load_stage(0, 0);

    for (int i = 0; i < niter; i++) {
        const int cur = i & 1;
        if (i + 1 < niter) { load_stage(i + 1, cur ^ 1); CP_WAIT1(); }
        else               { CP_WAIT0(); }
        __syncthreads();

        const uint32_t sA = base + cur * STG;
        const uint32_t sB = sA + TILEA;
        const uint32_t aBase = sA + (uint32_t)(wm * 32 + (lane & 15)) * ROWB + (uint32_t)(lane >> 4) * 16;
        const uint32_t bBase = sB + (uint32_t)(wn * 64 + (lane & 7) + ((lane >> 4) << 3)) * ROWB
                                  + (uint32_t)(((lane >> 3) & 1) << 4);

        #pragma unroll
        for (int ks = 0; ks < 4; ks++) {
            uint32_t af[2][4], bfr[4][4];
            ldsm4(af[0], aBase + ks * 32);
            ldsm4(af[1], aBase + 16 * ROWB + ks * 32);
            #pragma unroll
            for (int ni = 0; ni < 4; ni++)
                ldsm4(bfr[ni], bBase + ni * 16 * ROWB + ks * 32);
            #pragma unroll
            for (int mi = 0; mi < 2; mi++)
                #pragma unroll
                for (int ni = 0; ni < 4; ni++) {
                    mma_bf16(acc[mi][2 * ni],     af[mi], &bfr[ni][0]);
                    mma_bf16(acc[mi][2 * ni + 1], af[mi], &bfr[ni][2]);
                }
        }
        __syncthreads();
    }

    const int ncol0 = n0 + wn * 64 + (lane & 3) * 2;
    #pragma unroll
    for (int mi = 0; mi < 2; mi++) {
        const int ml = wm * 32 + mi * 16 + (lane >> 2);
        #pragma unroll
        for (int half = 0; half < 2; half++) {
            const int m = m0 + ml + half * 8;
            if (m >= Mreal) continue;
            size_t orow = outmode ? ((size_t)(m & 31) * T_STEPS + (m >> 5)) : (size_t)m;
            float* cr = C + orow * Ncols + ncol0;
            #pragma unroll
            for (int nj = 0; nj < 8; nj++) {
                const int c = ncol0 + nj * 8;
                float b0 = bias ? bias[c] : 0.f;
                float b1 = bias ? bias[c + 1] : 0.f;
                float2 v;
                v.x = acc[mi][nj][half * 2 + 0] + b0;
                v.y = acc[mi][nj][half * 2 + 1] + b1;
                *(float2*)(cr + nj * 8) = v;
            }
        }
    }
}

// single-job GEMM (projection)
__global__ void __launch_bounds__(256) mma_gemm(
    const __nv_bfloat16* __restrict__ Ah, const __nv_bfloat16* __restrict__ Al,
    const __nv_bfloat16* __restrict__ Bh, const __nv_bfloat16* __restrict__ Bl,
    int K, const float* __restrict__ bias, float* __restrict__ C,
    int Mreal, int Ncols, int outmode)
{
    extern __shared__ __align__(128) char sm[];
    gemm_tile(Ah, Al, Bh, Bl, K, bias, C, Mreal, Ncols, outmode,
              blockIdx.x * 128, blockIdx.y * 128, sm);
}

// all 5 precompute GEMMs in one launch (block-range dispatch)
struct GemmJob {
    const __nv_bfloat16 *Ah, *Al, *Bh, *Bl;
    int K;
    const float* bias;
    float* C;
    int Mreal, Ncols, mw, base;
};
struct GemmJobs { GemmJob j[5]; };

__global__ void __launch_bounds__(256) gemm_all(GemmJobs jobs)
{
    extern __shared__ __align__(128) char sm[];
    const int bx = blockIdx.x;
    int s = 4;
    #pragma unroll
    for (int k = 1; k < 5; k++)
        if (bx < jobs.j[k].base) { s = k - 1; break; }
    const GemmJob jb = jobs.j[s];
    const int i = bx - jb.base;
    const int m0 = (i % jb.mw) * 128;
    const int n0 = (i / jb.mw) * 128;
    gemm_tile(jb.Ah, jb.Al, jb.Bh, jb.Bl, jb.K, jb.bias, jb.C,
              jb.Mreal, jb.Ncols, 0, m0, n0, sm);
}

// ---------------- decode step A via HMMA, K-split x4, ALL stages prefetched ----------------
// grid 80 = (20 col-tiles x 4 K-quarters) x 256 threads.
// 6 stages (3 passes x 2 chunks) all issued up-front as separate commit groups
// into 6 distinct smem regions (138 KB); consumed with progressive wait_group.
#define P_AROW 4608              // 32 * 144
#define P_STG  23040             // (32 + 128) * 144
#define P_SMEM (6 * P_STG)       // 138240

__global__ void __launch_bounds__(256) step_qghmma()
{
    extern __shared__ __align__(128) char psm[];
    const uint32_t base = smem_u32(psm);
    const int tid = threadIdx.x;
    const int lane = tid & 31;
    const int w = tid >> 5;
    const int nt = blockIdx.x % 20;
    const int ksp = blockIdx.x / 20;     // 0..3
    const int n0 = nt * 128;

    float acc[2][2][4];
    #pragma unroll
    for (int a = 0; a < 2; a++)
        #pragma unroll
        for (int b = 0; b < 2; b++)
            #pragma unroll
            for (int c = 0; c < 4; c++) acc[a][b][c] = 0.f;

    const int arow = tid >> 3;           // 0..31 (batch)
    const int lg = tid & 7;

    // ---- issue ALL 6 stages immediately (6 commit groups) ----
    #pragma unroll
    for (int i = 0; i < 6; i++) {
        const int p  = i >> 1;           // pass: 0 Ah*Bh, 1 Al*Bh, 2 Ah*Bl
        const int kc = ksp * 2 + (i & 1);
        const __nv_bfloat16* Ag = ((p == 1) ? g_hl : g_hh)
            + ((size_t)arow * 512 + kc * 64 + lg * 8);
        const __nv_bfloat16* Bbase = (p == 2) ? g_wsl : g_wsh;
        const uint32_t dA = base + i * P_STG;
        const uint32_t dB = dA + P_AROW;
        CP16(dA + arow * ROWB + lg * 16, Ag);
        #pragma unroll
        for (int j = 0; j < 4; j++) {
            const int r = arow + 32 * j;
            CP16(dB + r * ROWB + lg * 16,
                 Bbase + ((size_t)(n0 + r) * 512 + kc * 64 + lg * 8));
        }
        CP_COMMIT();
    }

    // ---- consume stages with progressive waits ----
    #pragma unroll
    for (int i = 0; i < 6; i++) {
        switch (i) {
            case 0: cp_waitn<5>(); break;
            case 1: cp_waitn<4>(); break;
            case 2: cp_waitn<3>(); break;
            case 3: cp_waitn<2>(); break;
            case 4: cp_waitn<1>(); break;
            default: cp_waitn<0>(); break;
        }
        __syncthreads();

        const uint32_t sA = base + i * P_STG;
        const uint32_t sB = sA + P_AROW;
        const uint32_t aBase = sA + (uint32_t)(lane & 15) * ROWB + (uint32_t)(lane >> 4) * 16;
        const uint32_t bBase = sB + (uint32_t)(w * 16 + (lane & 7) + ((lane >> 4) << 3)) * ROWB
                                  + (uint32_t)(((lane >> 3) & 1) << 4);

        #pragma unroll
        for (int ks = 0; ks < 4; ks++) {
            uint32_t af0[4], af1[4], bfr[4];
            ldsm4(af0, aBase + ks * 32);
            ldsm4(af1, aBase + 16 * ROWB + ks * 32);
            ldsm4(bfr, bBase + ks * 32);
            mma_bf16(acc[0][0], af0, &bfr[0]);
            mma_bf16(acc[0][1], af0, &bfr[2]);
            mma_bf16(acc[1][0], af1, &bfr[0]);
            mma_bf16(acc[1][1], af1, &bfr[2]);
        }
    }

    float* qp  = g_qp[ksp];
    float* ghp = g_ghp[ksp];
    const int ncol0 = n0 + w * 16 + (lane & 3) * 2;
    #pragma unroll
    for (int mi = 0; mi < 2; mi++) {
        #pragma unroll
        for (int half = 0; half < 2; half++) {
            const int b = mi * 16 + (lane >> 2) + half * 8;    // batch 0..31
            #pragma unroll
            for (int nj = 0; nj < 2; nj++) {
                #pragma unroll
                for (int e = 0; e < 2; e++) {
                    const int c = ncol0 + nj * 8 + e;          // stacked row
                    float v = acc[mi][nj][half * 2 + e];
                    if (ksp == 0) v += g_bstack[c];
                    if (c < 1024) qp[b * 1024 + c] = v;
                    else          ghp[(size_t)b * GDIM + (c - 1024)] = v;
                }
            }
        }
    }
}

// ---------------- fused decode step B+C (R12) + partial-sum consumption ----------------
__global__ void __cluster_dims__(4, 1, 1) __launch_bounds__(256) step_scoregate(
    int tstep,
    const float* __restrict__ cWo, const float* __restrict__ cbo,
    const float* __restrict__ fWo, const float* __restrict__ fbo,
    const int* __restrict__ cmask, const int* __restrict__ fmask)
{
    __shared__ __align__(16) float sq[1024];
    __shared__ float s_all[100];
    __shared__ float attn[2][S_LEN];
    __shared__ float s_ps[384];

    const int qd = blockIdx.x;
    const int b  = blockIdx.y;
    const int tid = threadIdx.x;
    const int lane = tid & 31;
    const int w = tid >> 5;

    // sum the 4 q partials for this batch into smem
    for (int i = tid; i < 1024; i += 256)
        sq[i] = g_qp[0][b * 1024 + i] + g_qp[1][b * 1024 + i]
              + g_qp[2][b * 1024 + i] + g_qp[3][b * 1024 + i];
    __syncthreads();

    for (int ui = w; ui < 25; ui += 8) {
        const int u = qd * 25 + ui;
        const int a = u / S_LEN;
        const int s = u % S_LEN;
        const float* kr = (a ? g_kf : g_kc) + (size_t)(s * BATCH + b) * HID;
        const float* qr = sq + a * 512;
        const float* Wo = a ? fWo : cWo;
        float sacc = 0.f;
        #pragma unroll
        for (int j = 0; j < 4; j++) {
            float4 kv = *(const float4*)(kr + j * 128 + lane * 4);
            float4 qv = *(const float4*)(qr + j * 128 + lane * 4);
            float4 wv = *(const float4*)(Wo + j * 128 + lane * 4);
            sacc = fmaf(wv.x, tanhx(qv.x + kv.x), sacc);
            sacc = fmaf(wv.y, tanhx(qv.y + kv.y), sacc);
            sacc = fmaf(wv.z, tanhx(qv.z + kv.z), sacc);
            sacc = fmaf(wv.w, tanhx(qv.w + kv.w), sacc);
        }
        #pragma unroll
        for (int o = 16; o; o >>= 1) sacc += __shfl_xor_sync(0xffffffffu, sacc, o);
        if (lane == 0) {
            const int* msk = a ? fmask : cmask;
            float v = sacc + (a ? fbo : cbo)[0];
            if (msk[s * BATCH + b] == 0) v = -INFINITY;
            __stcg(&g_score[(a * S_LEN + s) * BATCH + b], v);
        }
    }

    CLUSTER_ARRIVE();
    CLUSTER_WAIT();

    if (tid < 100) s_all[tid] = __ldcg(&g_score[tid * BATCH + b]);
    __syncthreads();

    if (w < 2) {
        const int a = w;
        float v0 = s_all[a * S_LEN + lane];
        float v1 = (lane < S_LEN - 32) ? s_all[a * S_LEN + 32 + lane] : -INFINITY;
        float mx = fmaxf(v0, v1);
        #pragma unroll
        for (int o = 16; o; o >>= 1) mx = fmaxf(mx, __shfl_xor_sync(0xffffffffu, mx, o));
        float e0 = __expf(v0 - mx);
        float e1 = (lane < S_LEN - 32) ? __expf(v1 - mx) : 0.f;
        float sm = e0 + e1;
        #pragma unroll
        for (int o = 16; o; o >>= 1) sm += __shfl_xor_sync(0xffffffffu, sm, o);
        float inv = __fdividef(1.f, sm);
        attn[a][lane] = e0 * inv;
        if (lane < S_LEN - 32) attn[a][32 + lane] = e1 * inv;
    }
    __syncthreads();

    const int j = qd * 128 + (tid & 127);
    const int shalf = tid >> 7;
    float gr = 0.f, gz = 0.f, gn = 0.f;
    const int sbeg = shalf * 25;
    #pragma unroll 1
    for (int s = sbeg; s < sbeg + 25; s++) {
        const float ac = attn[0][s];
        const float af = attn[1][s];
        const float* pc = g_Pc + (size_t)(s * BATCH + b) * GDIM;
        const float* pf = g_Pf + (size_t)(s * BATCH + b) * GDIM;
        gr = fmaf(ac, pc[j],        gr); gr = fmaf(af, pf[j],        gr);
        gz = fmaf(ac, pc[512 + j],  gz); gz = fmaf(af, pf[512 + j],  gz);
        gn = fmaf(ac, pc[1024 + j], gn); gn = fmaf(af, pf[1024 + j], gn);
    }
    if (shalf == 1) {
        s_ps[tid & 127]         = gr;
        s_ps[128 + (tid & 127)] = gz;
        s_ps[256 + (tid & 127)] = gn;
    }
    __syncthreads();
    if (shalf == 0) {
        gr += s_ps[tid];
        gz += s_ps[128 + tid];
        gn += s_ps[256 + tid];
        const float* gip = g_gipre + (size_t)(tstep * BATCH + b) * GDIM;
        const size_t gb = (size_t)b * GDIM;
        const float ghr = g_ghp[0][gb + j]        + g_ghp[1][gb + j]
                        + g_ghp[2][gb + j]        + g_ghp[3][gb + j];
        const float ghz = g_ghp[0][gb + 512 + j]  + g_ghp[1][gb + 512 + j]
                        + g_ghp[2][gb + 512 + j]  + g_ghp[3][gb + 512 + j];
        const float ghn = g_ghp[0][gb + 1024 + j] + g_ghp[1][gb + 1024 + j]
                        + g_ghp[2][gb + 1024 + j] + g_ghp[3][gb + 1024 + j];
        const float gir = gip[j]        + gr;
        const float giz = gip[512 + j]  + gz;
        const float gin = gip[1024 + j] + gn;
        const float r = sigx(gir + ghr);
        const float z = sigx(giz + ghz);
        const float n = tanhx(gin + r * ghn);
        const float hv = g_h[b * HID + j];
        const float hn = (1.f - z) * n + z * hv;
        g_h[b * HID + j] = hn;
        g_reluh[(size_t)(tstep * BATCH + b) * HID + j] = fmaxf(hn, 0.f);
        __nv_bfloat16 hi, lo;
        split_bf16(hn, hi, lo);
        g_hh[b * 512 + j] = hi;
        g_hl[b * 512 + j] = lo;
    }
}

// single-job conv (reluh, after loop)
__global__ void conv_split(const float* __restrict__ src, int ld, int colstart,
                           int R, int K, int Rpad,
                           __nv_bfloat16* __restrict__ hi, __nv_bfloat16* __restrict__ lo)
{
    const int gpr = K >> 3;
    const long total = (long)Rpad * gpr;
    for (long idx = (long)blockIdx.x * blockDim.x + threadIdx.x; idx < total;
         idx += (long)gridDim.x * blockDim.x) {
        int r = (int)(idx / gpr);
        int g = (int)(idx - (long)r * gpr);
        float v[8];
        if (r < R) {
            const float* p = src + (size_t)r * ld + colstart + g * 8;
            float4 u0 = *(const float4*)p;
            float4 u1 = *(const float4*)(p + 4);
            v[0] = u0.x; v[1] = u0.y; v[2] = u0.z; v[3] = u0.w;
            v[4] = u1.x; v[5] = u1.y; v[6] = u1.z; v[7] = u1.w;
        } else {
            #pragma unroll
            for (int j = 0; j < 8; j++) v[j] = 0.f;
        }
        __align__(16) unsigned short hb[8];
        __align__(16) unsigned short lb[8];
        #pragma unroll
        for (int j = 0; j < 8; j++) {
            __nv_bfloat16 h, l;
            split_bf16(v[j], h, l);
            hb[j] = reinterpret_cast<unsigned short&>(h);
            lb[j] = reinterpret_cast<unsigned short&>(l);
        }
        size_t o = (size_t)r * K + (size_t)g * 8;
        *(uint4*)(hi + o) = *(const uint4*)hb;
        *(uint4*)(lo + o) = *(const uint4*)lb;
    }
}

// ---------------- launcher ----------------
extern "C" void kernel_launch(void* const* d_in, const int* in_sizes, int n_in,
                              void* d_out, int out_size)
{
    (void)in_sizes; (void)n_in; (void)out_size;

    const float* c_memory = (const float*)d_in[0];
    const int*   c_mask   = (const int*)  d_in[1];
    const float* f_memory = (const float*)d_in[2];
    const int*   f_mask   = (const int*)  d_in[3];
    const float* hidden   = (const float*)d_in[4];
    const float* latent   = (const float*)d_in[6];
    const int*   target   = (const int*)  d_in[7];
    const float* emb      = (const float*)d_in[8];
    const float* cW_h = (const float*)d_in[9];
    const float* cb_h = (const float*)d_in[10];
    const float* cW_m = (const float*)d_in[11];
    const float* cb_m = (const float*)d_in[12];
    const float* cW_o = (const float*)d_in[13];
    const float* cb_o = (const float*)d_in[14];
    const float* fW_h = (const float*)d_in[15];
    const float* fb_h = (const float*)d_in[16];
    const float* fW_m = (const float*)d_in[17];
    const float* fb_m = (const float*)d_in[18];
    const float* fW_o = (const float*)d_in[19];
    const float* fb_o = (const float*)d_in[20];
    const float* W_ih = (const float*)d_in[21];
    const float* b_ih = (const float*)d_in[22];
    const float* W_hh = (const float*)d_in[23];
    const float* b_hh = (const float*)d_in[24];
    const float* W_pr = (const float*)d_in[25];
    const float* b_pr = (const float*)d_in[26];
    float* out = (float*)d_out;

    float *kc, *kf, *Pc, *Pf, *X, *Wg, *gipre, *reluh;
    cudaGetSymbolAddress((void**)&kc,    g_kc);
    cudaGetSymbolAddress((void**)&kf,    g_kf);
    cudaGetSymbolAddress((void**)&Pc,    g_Pc);
    cudaGetSymbolAddress((void**)&Pf,    g_Pf);
    cudaGetSymbolAddress((void**)&X,     g_X);
    cudaGetSymbolAddress((void**)&Wg,    g_Wg);
    cudaGetSymbolAddress((void**)&gipre, g_gipre);
    cudaGetSymbolAddress((void**)&reluh, g_reluh);

    __nv_bfloat16 *cmh, *cml, *fmh, *fml, *cwmh, *cwml, *fwmh, *fwml;
    __nv_bfloat16 *wcch, *wccl, *wcfh, *wcfl, *wgh, *wgl, *xh, *xl, *rhh, *rhl, *wph, *wpl;
    __nv_bfloat16 *wsh, *wsl;
    cudaGetSymbolAddress((void**)&cmh,  g_cmh);  cudaGetSymbolAddress((void**)&cml,  g_cml);
    cudaGetSymbolAddress((void**)&fmh,  g_fmh);  cudaGetSymbolAddress((void**)&fml,  g_fml);
    cudaGetSymbolAddress((void**)&cwmh, g_cwmh); cudaGetSymbolAddress((void**)&cwml, g_cwml);
    cudaGetSymbolAddress((void**)&fwmh, g_fwmh); cudaGetSymbolAddress((void**)&fwml, g_fwml);
    cudaGetSymbolAddress((void**)&wcch, g_wcch); cudaGetSymbolAddress((void**)&wccl, g_wccl);
    cudaGetSymbolAddress((void**)&wcfh, g_wcfh); cudaGetSymbolAddress((void**)&wcfl, g_wcfl);
    cudaGetSymbolAddress((void**)&wgh,  g_wgh);  cudaGetSymbolAddress((void**)&wgl,  g_wgl);
    cudaGetSymbolAddress((void**)&xh,   g_xh);   cudaGetSymbolAddress((void**)&xl,   g_xl);
    cudaGetSymbolAddress((void**)&rhh,  g_rhh);  cudaGetSymbolAddress((void**)&rhl,  g_rhl);
    cudaGetSymbolAddress((void**)&wph,  g_wph);  cudaGetSymbolAddress((void**)&wpl,  g_wpl);
    cudaGetSymbolAddress((void**)&wsh,  g_wsh);  cudaGetSymbolAddress((void**)&wsl,  g_wsl);

    cudaFuncSetAttribute(mma_gemm, cudaFuncAttributeMaxDynamicSharedMemorySize, GSMEM);
    cudaFuncSetAttribute(gemm_all, cudaFuncAttributeMaxDynamicSharedMemorySize, GSMEM);
    cudaFuncSetAttribute(step_qghmma, cudaFuncAttributeMaxDynamicSharedMemorySize, P_SMEM);

    // ---- prologue: 3 launches ----
    gather_all<<<2522, 256>>>(target, emb, latent, W_ih, hidden, cb_h, fb_h, b_hh);

    ConvJobs cj;
    long base = 0;
    auto setc = [&](int i, const float* src, int ld, int cs, int R, int K, int Rpad,
                    __nv_bfloat16* hi, __nv_bfloat16* lo) {
        cj.j[i] = ConvJob{src, ld, cs, R, K, Rpad, hi, lo, base};
        base += (long)Rpad * (K >> 3);
    };
    setc(0, c_memory, 512, 0, 1600, 512, 1664, cmh, cml);
    setc(1, f_memory, 512, 0, 1600, 512, 1664, fmh, fml);
    setc(2, W_pr, 512, 0, 32000, 512, 32000, wph, wpl);
    setc(3, cW_m, 512, 0, 512, 512, 512, cwmh, cwml);
    setc(4, fW_m, 512, 0, 512, 512, 512, fwmh, fwml);
    setc(5, W_ih, 1600, 512,  1536, 512, 1536, wcch, wccl);
    setc(6, W_ih, 1600, 1024, 1536, 512, 1536, wcfh, wcfl);
    setc(7, Wg, 576, 0, 1536, 576, 1536, wgh, wgl);
    setc(8, X, 576, 0, 960, 576, 1024, xh, xl);
    setc(9,  cW_h, 512, 0, 512, 512, 512, wsh,               wsl);
    setc(10, fW_h, 512, 0, 512, 512, 512, wsh + 512 * 512,   wsl + 512 * 512);
    setc(11, W_hh, 512, 0, 1536, 512, 1536, wsh + 1024 * 512, wsl + 1024 * 512);
    cj.total = base;
    conv_all<<<8192, 256>>>(cj);

    GemmJobs gj;
    gj.j[0] = GemmJob{cmh, cml, cwmh, cwml, 512, cb_m, kc, 1600, 512, 13, 0};
    gj.j[1] = GemmJob{fmh, fml, fwmh, fwml, 512, fb_m, kf, 1600, 512, 13, 52};
    gj.j[2] = GemmJob{cmh, cml, wcch, wccl, 512, nullptr, Pc, 1600, GDIM, 13, 104};
    gj.j[3] = GemmJob{fmh, fml, wcfh, wcfl, 512, nullptr, Pf, 1600, GDIM, 13, 260};
    gj.j[4] = GemmJob{xh, xl, wgh, wgl, 576, b_ih, gipre, 960, GDIM, 8, 416};
    gemm_all<<<512, 256, GSMEM>>>(gj);

    // ---- sequential decode: 2 launches per step ----
    for (int t = 0; t < T_STEPS; t++) {
        step_qghmma<<<80, 256, P_SMEM>>>();
        step_scoregate<<<dim3(4, BATCH), 256>>>(t, cW_o, cb_o, fW_o, fb_o, c_mask, f_mask);
    }

    // ---- deferred vocabulary projection ----
    conv_split<<<2048, 256>>>(reluh, 512, 0, 960, 512, 1024, rhh, rhl);
    mma_gemm<<<dim3(8, 250), 256, GSMEM>>>(rhh, rhl, wph, wpl, 512, b_pr, out, 960, VOCAB, 1);
}